// round 12
// baseline (speedup 1.0000x reference)
#include <cuda_runtime.h>
#include <cuda_fp16.h>
#include <cstdint>

#define TOKENS 16384
#define HIDDEN 2048
#define NEXP   128
#define NOUT   256
#define TOPK   8
#define NCAND  32
#define TAU_L  6e-5f

typedef unsigned long long u64;

// ---------------- scratch (no allocs allowed) ----------------
__device__ float g_wT[HIDDEN * NOUT];        // [h][n] fp32 (certified recompute)
#define WP0_OFF 0
#define WP1_OFF ((size_t)NOUT * HIDDEN)
__device__ __half g_planes[2 * (size_t)NOUT * HIDDEN];
__device__ int g_nflag;
__device__ int g_flags[TOKENS];

// ---------------- PTX helpers (baseline ISA only) ----------------
__device__ __forceinline__ uint32_t smem_u32(const void* p) {
    uint32_t a;
    asm("{ .reg .u64 t; cvta.to.shared.u64 t, %1; cvt.u32.u64 %0, t; }" : "=r"(a) : "l"(p));
    return a;
}
__device__ __forceinline__ void cp16s(uint32_t saddr, const void* g) {
    asm volatile("cp.async.cg.shared.global [%0], [%1], 16;" :: "r"(saddr), "l"(g));
}
__device__ __forceinline__ void ldsm4(uint32_t* r, uint32_t a) {
    asm volatile("ldmatrix.sync.aligned.m8n8.x4.shared.b16 {%0,%1,%2,%3}, [%4];"
                 : "=r"(r[0]), "=r"(r[1]), "=r"(r[2]), "=r"(r[3]) : "r"(a));
}
__device__ __forceinline__ void mma16816(float* d, const uint32_t* a, const uint32_t* b) {
    asm volatile(
        "mma.sync.aligned.m16n8k16.row.col.f32.f16.f16.f32 "
        "{%0,%1,%2,%3}, {%4,%5,%6,%7}, {%8,%9}, {%0,%1,%2,%3};"
        : "+f"(d[0]), "+f"(d[1]), "+f"(d[2]), "+f"(d[3])
        : "r"(a[0]), "r"(a[1]), "r"(a[2]), "r"(a[3]), "r"(b[0]), "r"(b[1]));
}
#define GBAR(g) asm volatile("bar.sync %0, %1;" :: "r"((g) + 1), "r"(128) : "memory")

// fp16 2-plane split: v = p0 + p1 + O(2^-22 v)
__device__ __forceinline__ void split2(float v, __half& a0, __half& a1) {
    a0 = __float2half_rn(v);
    a1 = __float2half_rn(v - __half2float(a0));
}

// ---------------------------------------------------------------------------
// Weight prep: fp16 planes + fp32 transpose + flag reset
// ---------------------------------------------------------------------------
__global__ void wprep_kernel(const float* __restrict__ wo,
                             const float* __restrict__ wb) {
    if (blockIdx.x == 0 && threadIdx.x == 0) g_nflag = 0;
    size_t i4 = (size_t)blockIdx.x * 256 + threadIdx.x;
    if (i4 >= (size_t)NOUT * HIDDEN / 4) return;
    int n  = (int)(i4 / (HIDDEN / 4));
    int c4 = (int)(i4 % (HIDDEN / 4)) * 4;
    const float* src = (n < NEXP) ? &wo[(size_t)n * HIDDEN + c4]
                                  : &wb[(size_t)(n - NEXP) * HIDDEN + c4];
    float4 v = *(const float4*)src;
    __half a0[4], a1[4];
    split2(v.x, a0[0], a1[0]);
    split2(v.y, a0[1], a1[1]);
    split2(v.z, a0[2], a1[2]);
    split2(v.w, a0[3], a1[3]);
    size_t e = (size_t)n * HIDDEN + c4;
    *(uint2*)&g_planes[WP0_OFF + e] = *(uint2*)a0;
    *(uint2*)&g_planes[WP1_OFF + e] = *(uint2*)a1;
    g_wT[(size_t)(c4 + 0) * NOUT + n] = v.x;
    g_wT[(size_t)(c4 + 1) * NOUT + n] = v.y;
    g_wT[(size_t)(c4 + 2) * NOUT + n] = v.z;
    g_wT[(size_t)(c4 + 3) * NOUT + n] = v.w;
}

// ---------------------------------------------------------------------------
// Precise exp + warp reductions
// ---------------------------------------------------------------------------
__device__ __forceinline__ float exp_precise(float xx) {
    float kf = rintf(xx * 1.4426950408889634f);
    float r  = fmaf(kf, -0.693145751953125f, xx);
    r = fmaf(kf, -1.42860676533018704e-06f, r);
    float p = 1.98412698412698413e-04f;
    p = fmaf(p, r, 1.38888888888888889e-03f);
    p = fmaf(p, r, 8.33333333333333333e-03f);
    p = fmaf(p, r, 4.16666666666666667e-02f);
    p = fmaf(p, r, 1.66666666666666667e-01f);
    p = fmaf(p, r, 0.5f);
    p = fmaf(p, r, 1.0f);
    p = fmaf(p, r, 1.0f);
    int ki = (int)kf;
    return p * __int_as_float((ki + 127) << 23);
}
__device__ __forceinline__ float warpMax(float v) {
#pragma unroll
    for (int o = 16; o; o >>= 1) v = fmaxf(v, __shfl_xor_sync(0xffffffffu, v, o));
    return v;
}
__device__ __forceinline__ float warpSum(float v) {
#pragma unroll
    for (int o = 16; o; o >>= 1) v += __shfl_xor_sync(0xffffffffu, v, o);
    return v;
}

// ---------------------------------------------------------------------------
// Fused GEMM + routing. CTA = 64 tokens x 256 experts, 256 threads (2x4 warps).
// 1 sync/stage; x converted to fp16 planes off the tensor critical path.
// Thread t<128 OWNS half-row (r=t>>1, h=t&1) of the x32 buffer: it issues the
// cp.async for it AND converts it -> no cross-thread race on the single buffer.
// ---------------------------------------------------------------------------
#define ROWB    80
#define STAGEB  (640 * ROWB)          // 51200 B
#define X32OFF  (2 * STAGEB)          // 102400
#define NKB     (HIDDEN / 32)         // 64 stages
#define SLSTR   258
#define DSMEM   (X32OFF + 64 * 128)   // 110592 B

__global__ __launch_bounds__(256, 2) void fused_kernel(const float* __restrict__ x,
                                                       float* __restrict__ out) {
    extern __shared__ char dsm[];
    const uint32_t sbase = smem_u32(dsm);
    const uint32_t x32b  = sbase + X32OFF;
    float* slog = (float*)dsm;

    const int tid    = threadIdx.x;
    const int lane   = tid & 31;
    const int wid    = tid >> 5;
    const int warp_m = wid & 1;
    const int warp_n = wid >> 1;
    const int m0     = blockIdx.x * 64;

    // B loader: 2048 chunks, 8 per thread
    uint32_t smoffB[8], goffB[8];
#pragma unroll
    for (int i = 0; i < 8; ++i) {
        int cid = tid + i * 256;
        int row = cid >> 2, seg = cid & 3;
        smoffB[i] = (uint32_t)((128 + row) * ROWB + seg * 16);
        int q = row >> 8, r = row & 255;
        goffB[i] = (uint32_t)(((q ? WP1_OFF : WP0_OFF) + (size_t)r * HIDDEN) * 2 + seg * 16);
    }
    const char* gw = (const char*)g_planes;
    const char* gx = (const char*)x;

    // x32 ownership: thread t<128 owns half-row (xr, xh)
    const int xr = tid >> 1;
    const int xh = tid & 1;
    const uint32_t xsm = x32b + xr * 128 + xh * 64;                       // smem
    const size_t   xgo = ((size_t)(m0 + xr) * HIDDEN) * 4 + xh * 64;     // gmem bytes

    float acc[2][8][4];
#pragma unroll
    for (int mf = 0; mf < 2; ++mf)
#pragma unroll
        for (int nf = 0; nf < 8; ++nf)
#pragma unroll
            for (int c = 0; c < 4; ++c) acc[mf][nf][c] = 0.f;

    const int a_row = lane & 15;
    const int a_col = (lane >> 4) << 3;
    const int b_row = ((lane >> 4) & 1) * 8 + (lane & 7);
    const int b_col = ((lane >> 3) & 1) * 8;

    // convert x32 (k-block data) -> A planes of stage buffer `dst`
    auto convert_x = [&](char* dst) {
        if (tid < 128) {
            const float4* src = (const float4*)(dsm + X32OFF + xr * 128 + xh * 64);
#pragma unroll
            for (int q = 0; q < 4; ++q) {
                float4 v = src[q];
                __half a0x, a1x, a0y, a1y, a0z, a1z, a0w, a1w;
                split2(v.x, a0x, a1x); split2(v.y, a0y, a1y);
                split2(v.z, a0z, a1z); split2(v.w, a0w, a1w);
                __half2 p0a = __halves2half2(a0x, a0y), p0b = __halves2half2(a0z, a0w);
                __half2 p1a = __halves2half2(a1x, a1y), p1b = __halves2half2(a1z, a1w);
                uint2 u0, u1;
                u0.x = *(uint32_t*)&p0a; u0.y = *(uint32_t*)&p0b;
                u1.x = *(uint32_t*)&p1a; u1.y = *(uint32_t*)&p1b;
                *(uint2*)(dst + xr * ROWB + xh * 32 + q * 8)        = u0;
                *(uint2*)(dst + (64 + xr) * ROWB + xh * 32 + q * 8) = u1;
            }
        }
    };
    auto issue_x = [&](int kblk) {
        if (tid < 128) {
#pragma unroll
            for (int i = 0; i < 4; ++i)
                cp16s(xsm + i * 16, gx + xgo + (size_t)kblk * 128 + i * 16);
        }
    };

    // ---- preamble: stage 0 ----
#pragma unroll
    for (int i = 0; i < 8; ++i) cp16s(sbase + smoffB[i], gw + goffB[i]);
    issue_x(0);
    asm volatile("cp.async.commit_group;");
    asm volatile("cp.async.wait_group 0;");
    __syncthreads();
    convert_x(dsm);                  // A[0] into stage 0
    issue_x(1);
    asm volatile("cp.async.commit_group;");

    for (int kb = 0; kb < NKB; ++kb) {
        const uint32_t cur = sbase + (kb & 1) * STAGEB;
        __syncthreads();             // A[kb] visible; B[kb] arrival known from last wait
        if (kb + 1 < NKB) {
            const uint32_t nxt = sbase + ((kb + 1) & 1) * STAGEB;
            const uint32_t kb1 = (uint32_t)(kb + 1);
#pragma unroll
            for (int i = 0; i < 8; ++i) cp16s(nxt + smoffB[i], gw + goffB[i] + kb1 * 64);
            asm volatile("cp.async.commit_group;");
        }

        // ---- MMAs for stage kb ----
#pragma unroll
        for (int s = 0; s < 2; ++s) {
            uint32_t af[2][2][4];
#pragma unroll
            for (int p = 0; p < 2; ++p)
#pragma unroll
                for (int mf = 0; mf < 2; ++mf) {
                    uint32_t addr = cur
                                  + (p * 64 + warp_m * 32 + mf * 16 + a_row) * ROWB
                                  + (s * 16 + a_col) * 2;
                    ldsm4(af[p][mf], addr);
                }
#pragma unroll
            for (int pb = 0; pb < 2; ++pb) {
                uint32_t bf[4][4];
#pragma unroll
                for (int np = 0; np < 4; ++np) {
                    uint32_t addr = cur
                                  + (128 + pb * 256 + warp_n * 64 + np * 16 + b_row) * ROWB
                                  + (s * 16 + b_col) * 2;
                    ldsm4(bf[np], addr);
                }
                const int na = 2 - pb;
#pragma unroll
                for (int pa = 0; pa < 2; ++pa) {
                    if (pa >= na) break;
#pragma unroll
                    for (int mf = 0; mf < 2; ++mf)
#pragma unroll
                        for (int nf = 0; nf < 8; ++nf)
                            mma16816(acc[mf][nf], af[pa][mf], &bf[nf >> 1][(nf & 1) * 2]);
                }
            }
        }

        // ---- off-critical-path: wait loads, convert next A, issue next x ----
        asm volatile("cp.async.wait_group 0;");   // B[kb+1] + x32[kb+1] complete
        if (kb + 1 < NKB) convert_x(dsm + ((kb + 1) & 1) * STAGEB);
        if (kb + 2 < NKB) {
            issue_x(kb + 2);
            asm volatile("cp.async.commit_group;");
        }
    }

    // ---- epilogue: accs -> smem logits ----
    __syncthreads();
#pragma unroll
    for (int mf = 0; mf < 2; ++mf)
#pragma unroll
        for (int nf = 0; nf < 8; ++nf) {
            const int row = warp_m * 32 + mf * 16 + (lane >> 2);
            const int col = warp_n * 64 + nf * 8 + (lane & 3) * 2;
            *(float2*)&slog[(size_t)row * SLSTR + col] =
                make_float2(acc[mf][nf][0], acc[mf][nf][1]);
            *(float2*)&slog[(size_t)(row + 8) * SLSTR + col] =
                make_float2(acc[mf][nf][2], acc[mf][nf][3]);
        }
    __syncthreads();

    // ---- routing: 2 groups of 128 threads, 32 tokens each ----
    const int g   = tid >> 7;
    const int e   = tid & 127;
    const int gw2 = (tid >> 5) & 3;
    const int gl  = tid & 31;

    __shared__ float s4m1[2][4], s4m2[2][4], s4s1[2][4], s4s2[2][4];
    __shared__ float sbg[2][NEXP];
    __shared__ float bvhlg[2][NEXP];
    __shared__ float candpg[2][NCAND];
    __shared__ float candflg[2][NCAND];
    __shared__ int   candeg[2][NCAND];
    __shared__ float candlg[2][NCAND];
    __shared__ float toppg[2][TOPK];
    __shared__ int   topeg[2][TOPK];

    for (int it = 0; it < 32; ++it) {
        const int t  = g * 32 + it;
        const int tg = m0 + t;
        float fl = slog[(size_t)t * SLSTR + e];
        float bl = slog[(size_t)t * SLSTR + 128 + e];

        float wm1 = warpMax(fl);
        float wm2 = warpMax(bl);
        if (gl == 0) { s4m1[g][gw2] = wm1; s4m2[g][gw2] = wm2; }
        GBAR(g);
        float m1 = fmaxf(fmaxf(s4m1[g][0], s4m1[g][1]), fmaxf(s4m1[g][2], s4m1[g][3]));
        float m2 = fmaxf(fmaxf(s4m2[g][0], s4m2[g][1]), fmaxf(s4m2[g][2], s4m2[g][3]));
        float p = exp_precise(fl - m1);
        float q = exp_precise(bl - m2);
        float ws1 = warpSum(p);
        float ws2 = warpSum(q);
        if (gl == 0) { s4s1[g][gw2] = ws1; s4s2[g][gw2] = ws2; }
        GBAR(g);
        float s1 = s4s1[g][0] + s4s1[g][1] + s4s1[g][2] + s4s1[g][3];
        float s2 = s4s2[g][0] + s4s2[g][1] + s4s2[g][2] + s4s2[g][3];
        float prob  = __fdiv_rn(p, s1);
        out[(size_t)tg * NEXP + e] = prob;
        float bprob = __fdiv_rn(q, s2);
        sbg[g][e] = bprob;
        GBAR(g);

        int r = 0;
#pragma unroll 8
        for (int j = 0; j < NEXP; ++j) {
            float v = sbg[g][j];
            r += (v > bprob) || (v == bprob && j < e);
        }
        bvhlg[g][r] = bl;
        if (r < NCAND) { candeg[g][r] = e; candpg[g][r] = prob; candflg[g][r] = fl; }
        GBAR(g);

        if (e < NCAND) {
            float cp = candpg[g][e];
            int r2 = 0;
#pragma unroll
            for (int j = 0; j < NCAND; ++j) {
                float v = candpg[g][j];
                r2 += (v > cp) || (v == cp && j < e);
            }
            candlg[g][r2] = candflg[g][e];
            if (r2 < TOPK) { topeg[g][r2] = candeg[g][e]; toppg[g][r2] = cp; }
        }
        GBAR(g);

        if (e == 0) {
            float s = 0.f;
#pragma unroll
            for (int k = 0; k < TOPK; ++k) s += toppg[g][k];
            float* ov = out + (size_t)TOKENS * NEXP + (size_t)tg * TOPK;
            float* oi = out + (size_t)TOKENS * NEXP + (size_t)TOKENS * TOPK + (size_t)tg * TOPK;
#pragma unroll
            for (int k = 0; k < TOPK; ++k) {
                ov[k] = __fdiv_rn(toppg[g][k], s);
                oi[k] = (float)topeg[g][k];
            }
            bool flag = (bvhlg[g][NCAND - 1] - bvhlg[g][NCAND] < TAU_L) ||
                        (candlg[g][TOPK - 1] - candlg[g][TOPK] < TAU_L);
#pragma unroll
            for (int k = 0; k < TOPK - 1; ++k)
                flag |= (candlg[g][k] - candlg[g][k + 1] < TAU_L);
            if (flag) {
                int pos = atomicAdd(&g_nflag, 1);
                g_flags[pos] = tg;
            }
        }
        GBAR(g);
    }
}

// ---------------------------------------------------------------------------
// Certified recompute + re-route, 16 tokens per block.
// Thread = (token j = tid>>4, 16 consecutive experts). Per-(t,n) chain is
// op-identical to the certified ordering. 3-buffer w ring, depth-2 prefetch.
// Dynamic smem: xs 16x8KB=131072 | ws 3x16384=49152 | sl 16x1KB=16384
// ---------------------------------------------------------------------------
#define RC_XS   0
#define RC_WS   131072
#define RC_SL   (RC_WS + 49152)
#define RC_SMEM (RC_SL + 16384)      // 196608

__global__ __launch_bounds__(256, 1) void recroute_kernel(const float* __restrict__ x,
                                                          float* __restrict__ out) {
    extern __shared__ char rsm[];
    float* xs  = (float*)(rsm + RC_XS);     // [16][2048]
    float* wsm = (float*)(rsm + RC_WS);     // [3][16*256]
    float* sl  = (float*)(rsm + RC_SL);     // [16][256]
    const uint32_t xsb = smem_u32(xs);
    const uint32_t wsb = smem_u32(wsm);

    __shared__ int   s_tl[16];
    __shared__ float s4m1[2][4], s4m2[2][4], s4s1[2][4], s4s2[2][4];
    __shared__ float sbg[2][NEXP];
    __shared__ float candpg[2][NCAND];
    __shared__ int   candeg[2][NCAND];
    __shared__ float toppg[2][TOPK];
    __shared__ int   topeg[2][TOPK];

    const int tid  = threadIdx.x;
    const int cnt  = g_nflag;
    const int ngroups = (cnt + 15) >> 4;
    const int j    = tid >> 4;          // token slot 0..15
    const int n16  = (tid & 15) * 16;   // 16 consecutive experts

    for (int gi = blockIdx.x; gi < ngroups; gi += gridDim.x) {
        if (tid < 16) {
            int idx = gi * 16 + tid;
            s_tl[tid] = g_flags[idx < cnt ? idx : cnt - 1];
        }
        asm volatile("cp.async.wait_group 0;");
        __syncthreads();

        // xs: 16 rows x 8KB = 8192 chunks, 32 per thread
#pragma unroll
        for (int i = 0; i < 32; ++i) {
            int cid = tid + i * 256;
            int j2 = cid >> 9, c = cid & 511;
            cp16s(xsb + j2 * 8192 + c * 16,
                  (const char*)(x + (size_t)s_tl[j2] * HIDDEN) + c * 16);
        }
#pragma unroll
        for (int i = 0; i < 4; ++i) {
            int cid = tid + i * 256;
            cp16s(wsb + cid * 16, (const char*)g_wT + cid * 16);
        }
        asm volatile("cp.async.commit_group;");
#pragma unroll
        for (int i = 0; i < 4; ++i) {
            int cid = tid + i * 256;
            cp16s(wsb + 16384 + cid * 16, (const char*)g_wT + 16384 + cid * 16);
        }
        asm volatile("cp.async.commit_group;");

        float acc[16], cmp[16];
#pragma unroll
        for (int c = 0; c < 16; ++c) { acc[c] = 0.f; cmp[c] = 0.f; }

        for (int kb = 0; kb < 128; ++kb) {
            asm volatile("cp.async.wait_group 1;");
            __syncthreads();
            if (kb + 2 < 128) {
                uint32_t buf = (uint32_t)((kb + 2) % 3) * 16384;
                const char* gsrc = (const char*)g_wT + (size_t)(kb + 2) * 16384;
#pragma unroll
                for (int i = 0; i < 4; ++i) {
                    int cid = tid + i * 256;
                    cp16s(wsb + buf + cid * 16, gsrc + cid * 16);
                }
                asm volatile("cp.async.commit_group;");
            }
            const float* wcur = wsm + (kb % 3) * 4096;
            const float* xrow = xs + j * 2048 + kb * 16;
            float bp[16];
#pragma unroll
            for (int c = 0; c < 16; ++c) bp[c] = 0.f;
#pragma unroll
            for (int k = 0; k < 16; ++k) {
                float xv = xrow[k];
                const float* wr = &wcur[k * NOUT + n16];
#pragma unroll
                for (int c4 = 0; c4 < 4; ++c4) {
                    float4 w4 = *(const float4*)&wr[c4 * 4];
                    bp[c4 * 4 + 0] = fmaf(xv, w4.x, bp[c4 * 4 + 0]);
                    bp[c4 * 4 + 1] = fmaf(xv, w4.y, bp[c4 * 4 + 1]);
                    bp[c4 * 4 + 2] = fmaf(xv, w4.z, bp[c4 * 4 + 2]);
                    bp[c4 * 4 + 3] = fmaf(xv, w4.w, bp[c4 * 4 + 3]);
                }
            }
#pragma unroll
            for (int c = 0; c < 16; ++c) {
                float y = bp[c] - cmp[c];
                float s = acc[c] + y;
                cmp[c] = (s - acc[c]) - y;
                acc[c] = s;
            }
        }
#pragma unroll
        for (int c4 = 0; c4 < 4; ++c4)
            *(float4*)&sl[j * 256 + n16 + c4 * 4] =
                make_float4(acc[c4 * 4], acc[c4 * 4 + 1], acc[c4 * 4 + 2], acc[c4 * 4 + 3]);
        __syncthreads();

        // ---- route 16 tokens: 2 groups of 128 threads, 8 tokens each ----
        const int g   = tid >> 7;
        const int e   = tid & 127;
        const int gw2 = (tid >> 5) & 3;
        const int gl  = tid & 31;

        for (int it = 0; it < 8; ++it) {
            const int j2 = g * 8 + it;
            if (gi * 16 + j2 >= cnt) break;
            const int t = s_tl[j2];
            float fl = sl[j2 * 256 + e];
            float bl = sl[j2 * 256 + 128 + e];

            float wm1 = warpMax(fl);
            float wm2 = warpMax(bl);
            if (gl == 0) { s4m1[g][gw2] = wm1; s4m2[g][gw2] = wm2; }
            GBAR(g);
            float m1 = fmaxf(fmaxf(s4m1[g][0], s4m1[g][1]), fmaxf(s4m1[g][2], s4m1[g][3]));
            float m2 = fmaxf(fmaxf(s4m2[g][0], s4m2[g][1]), fmaxf(s4m2[g][2], s4m2[g][3]));
            float p = exp_precise(fl - m1);
            float q = exp_precise(bl - m2);
            float ws1 = warpSum(p);
            float ws2 = warpSum(q);
            if (gl == 0) { s4s1[g][gw2] = ws1; s4s2[g][gw2] = ws2; }
            GBAR(g);
            float s1 = s4s1[g][0] + s4s1[g][1] + s4s1[g][2] + s4s1[g][3];
            float s2 = s4s2[g][0] + s4s2[g][1] + s4s2[g][2] + s4s2[g][3];
            float prob  = __fdiv_rn(p, s1);
            out[(size_t)t * NEXP + e] = prob;
            float bprob = __fdiv_rn(q, s2);
            sbg[g][e] = bprob;
            GBAR(g);

            int r = 0;
#pragma unroll 8
            for (int jj = 0; jj < NEXP; ++jj) {
                float v = sbg[g][jj];
                r += (v > bprob) || (v == bprob && jj < e);
            }
            if (r < NCAND) { candeg[g][r] = e; candpg[g][r] = prob; }
            GBAR(g);

            if (e < NCAND) {
                float cp = candpg[g][e];
                int r2 = 0;
#pragma unroll
                for (int jj = 0; jj < NCAND; ++jj) {
                    float v = candpg[g][jj];
                    r2 += (v > cp) || (v == cp && jj < e);
                }
                if (r2 < TOPK) { topeg[g][r2] = candeg[g][e]; toppg[g][r2] = cp; }
            }
            GBAR(g);

            if (e == 0) {
                float s = 0.f;
#pragma unroll
                for (int k = 0; k < TOPK; ++k) s += toppg[g][k];
                float* ov = out + (size_t)TOKENS * NEXP + (size_t)t * TOPK;
                float* oi = out + (size_t)TOKENS * NEXP + (size_t)TOKENS * TOPK + (size_t)t * TOPK;
#pragma unroll
                for (int k = 0; k < TOPK; ++k) {
                    ov[k] = __fdiv_rn(toppg[g][k], s);
                    oi[k] = (float)topeg[g][k];
                }
            }
            GBAR(g);
        }
        __syncthreads();
    }
}

// ---------------------------------------------------------------------------
extern "C" void kernel_launch(void* const* d_in, const int* in_sizes, int n_in,
                              void* d_out, int out_size) {
    const float* x  = (const float*)d_in[0];
    const float* wo = (const float*)d_in[1];
    const float* wb = (const float*)d_in[2];
    float* out = (float*)d_out;

    cudaFuncSetAttribute(fused_kernel, cudaFuncAttributeMaxDynamicSharedMemorySize, DSMEM);
    cudaFuncSetAttribute(recroute_kernel, cudaFuncAttributeMaxDynamicSharedMemorySize, RC_SMEM);

    wprep_kernel<<<(NOUT * HIDDEN / 4 + 255) / 256, 256>>>(wo, wb);
    fused_kernel<<<TOKENS / 64, 256, DSMEM>>>(x, out);
    recroute_kernel<<<256, 256, RC_SMEM>>>(x, out);
}

// round 13
// speedup vs baseline: 3.5595x; 3.5595x over previous
#include <cuda_runtime.h>
#include <cuda_fp16.h>
#include <cstdint>

#define TOKENS 16384
#define HIDDEN 2048
#define NEXP   128
#define NOUT   256
#define TOPK   8
#define NCAND  32
#define TAU_L  6e-5f

typedef unsigned long long u64;

// ---------------- scratch (no allocs allowed) ----------------
__device__ float g_wT[HIDDEN * NOUT];        // [h][n] fp32 (certified recompute)
#define WP0_OFF 0
#define WP1_OFF ((size_t)NOUT * HIDDEN)
__device__ __half g_planes[2 * (size_t)NOUT * HIDDEN];
__device__ int g_nflag;
__device__ int g_flags[TOKENS];

// ---------------- PTX helpers (baseline ISA only) ----------------
__device__ __forceinline__ uint32_t smem_u32(const void* p) {
    uint32_t a;
    asm("{ .reg .u64 t; cvta.to.shared.u64 t, %1; cvt.u32.u64 %0, t; }" : "=r"(a) : "l"(p));
    return a;
}
__device__ __forceinline__ void cp16s(uint32_t saddr, const void* g) {
    asm volatile("cp.async.cg.shared.global [%0], [%1], 16;" :: "r"(saddr), "l"(g));
}
__device__ __forceinline__ void ldsm4(uint32_t* r, uint32_t a) {
    asm volatile("ldmatrix.sync.aligned.m8n8.x4.shared.b16 {%0,%1,%2,%3}, [%4];"
                 : "=r"(r[0]), "=r"(r[1]), "=r"(r[2]), "=r"(r[3]) : "r"(a));
}
__device__ __forceinline__ void mma16816(float* d, const uint32_t* a, const uint32_t* b) {
    asm volatile(
        "mma.sync.aligned.m16n8k16.row.col.f32.f16.f16.f32 "
        "{%0,%1,%2,%3}, {%4,%5,%6,%7}, {%8,%9}, {%0,%1,%2,%3};"
        : "+f"(d[0]), "+f"(d[1]), "+f"(d[2]), "+f"(d[3])
        : "r"(a[0]), "r"(a[1]), "r"(a[2]), "r"(a[3]), "r"(b[0]), "r"(b[1]));
}
#define GBAR(g) asm volatile("bar.sync %0, %1;" :: "r"((g) + 1), "r"(128) : "memory")

// fp16 2-plane split: v = p0 + p1 + O(2^-22 v)
__device__ __forceinline__ void split2(float v, __half& a0, __half& a1) {
    a0 = __float2half_rn(v);
    a1 = __float2half_rn(v - __half2float(a0));
}

// ---------------------------------------------------------------------------
// Weight prep: fp16 planes + fp32 transpose + flag reset
// ---------------------------------------------------------------------------
__global__ void wprep_kernel(const float* __restrict__ wo,
                             const float* __restrict__ wb) {
    if (blockIdx.x == 0 && threadIdx.x == 0) g_nflag = 0;
    size_t i4 = (size_t)blockIdx.x * 256 + threadIdx.x;
    if (i4 >= (size_t)NOUT * HIDDEN / 4) return;
    int n  = (int)(i4 / (HIDDEN / 4));
    int c4 = (int)(i4 % (HIDDEN / 4)) * 4;
    const float* src = (n < NEXP) ? &wo[(size_t)n * HIDDEN + c4]
                                  : &wb[(size_t)(n - NEXP) * HIDDEN + c4];
    float4 v = *(const float4*)src;
    __half a0[4], a1[4];
    split2(v.x, a0[0], a1[0]);
    split2(v.y, a0[1], a1[1]);
    split2(v.z, a0[2], a1[2]);
    split2(v.w, a0[3], a1[3]);
    size_t e = (size_t)n * HIDDEN + c4;
    *(uint2*)&g_planes[WP0_OFF + e] = *(uint2*)a0;
    *(uint2*)&g_planes[WP1_OFF + e] = *(uint2*)a1;
    g_wT[(size_t)(c4 + 0) * NOUT + n] = v.x;
    g_wT[(size_t)(c4 + 1) * NOUT + n] = v.y;
    g_wT[(size_t)(c4 + 2) * NOUT + n] = v.z;
    g_wT[(size_t)(c4 + 3) * NOUT + n] = v.w;
}

// ---------------------------------------------------------------------------
// Precise exp + warp reductions
// ---------------------------------------------------------------------------
__device__ __forceinline__ float exp_precise(float xx) {
    float kf = rintf(xx * 1.4426950408889634f);
    float r  = fmaf(kf, -0.693145751953125f, xx);
    r = fmaf(kf, -1.42860676533018704e-06f, r);
    float p = 1.98412698412698413e-04f;
    p = fmaf(p, r, 1.38888888888888889e-03f);
    p = fmaf(p, r, 8.33333333333333333e-03f);
    p = fmaf(p, r, 4.16666666666666667e-02f);
    p = fmaf(p, r, 1.66666666666666667e-01f);
    p = fmaf(p, r, 0.5f);
    p = fmaf(p, r, 1.0f);
    p = fmaf(p, r, 1.0f);
    int ki = (int)kf;
    return p * __int_as_float((ki + 127) << 23);
}
__device__ __forceinline__ float warpMax(float v) {
#pragma unroll
    for (int o = 16; o; o >>= 1) v = fmaxf(v, __shfl_xor_sync(0xffffffffu, v, o));
    return v;
}
__device__ __forceinline__ float warpSum(float v) {
#pragma unroll
    for (int o = 16; o; o >>= 1) v += __shfl_xor_sync(0xffffffffu, v, o);
    return v;
}

// ---------------------------------------------------------------------------
// Fused GEMM + routing. CTA = 64 tokens x 256 experts, 256 threads (2x4 warps).
// x prefetched via LDG into registers one stage ahead; split+STS into the NEXT
// stage's A-plane region after the MMAs (off the critical path). One sync and
// one cp.async group (B) per stage, wait-at-end with full-stage overlap.
// A-plane bytes, split values, MMA order identical to certified rounds.
// ---------------------------------------------------------------------------
#define ROWB    80
#define STAGEB  (640 * ROWB)          // 51200 B
#define NKB     (HIDDEN / 32)         // 64 stages
#define SLSTR   258
#define DSMEM   (2 * STAGEB)          // 102400 B (slog 66048 fits)

__global__ __launch_bounds__(256, 2) void fused_kernel(const float* __restrict__ x,
                                                       float* __restrict__ out) {
    extern __shared__ char dsm[];
    const uint32_t sbase = smem_u32(dsm);
    float* slog = (float*)dsm;

    const int tid    = threadIdx.x;
    const int lane   = tid & 31;
    const int wid    = tid >> 5;
    const int warp_m = wid & 1;
    const int warp_n = wid >> 1;
    const int m0     = blockIdx.x * 64;

    // B loader: 2048 chunks, 8 per thread
    uint32_t smoffB[8], goffB[8];
#pragma unroll
    for (int i = 0; i < 8; ++i) {
        int cid = tid + i * 256;
        int row = cid >> 2, seg = cid & 3;
        smoffB[i] = (uint32_t)((128 + row) * ROWB + seg * 16);
        int q = row >> 8, r = row & 255;
        goffB[i] = (uint32_t)(((q ? WP1_OFF : WP0_OFF) + (size_t)r * HIDDEN) * 2 + seg * 16);
    }
    const char* gw = (const char*)g_planes;
    const char* gx = (const char*)x;

    // x ownership: thread t<128 owns half-row (xr, xh): 64 bytes per stage
    const int xr = tid >> 1;
    const int xh = tid & 1;
    const size_t xgo = ((size_t)(m0 + xr) * HIDDEN) * 4 + xh * 64;   // gmem bytes

    float acc[2][8][4];
#pragma unroll
    for (int mf = 0; mf < 2; ++mf)
#pragma unroll
        for (int nf = 0; nf < 8; ++nf)
#pragma unroll
            for (int c = 0; c < 4; ++c) acc[mf][nf][c] = 0.f;

    const int a_row = lane & 15;
    const int a_col = (lane >> 4) << 3;
    const int b_row = ((lane >> 4) & 1) * 8 + (lane & 7);
    const int b_col = ((lane >> 3) & 1) * 8;

    float4 xbuf[2][4];

    // split xv[4] -> A planes of stage buffer dst (bitwise == certified convert)
    auto sts_x = [&](char* dst, const float4* xv) {
#pragma unroll
        for (int q = 0; q < 4; ++q) {
            float4 v = xv[q];
            __half a0x, a1x, a0y, a1y, a0z, a1z, a0w, a1w;
            split2(v.x, a0x, a1x); split2(v.y, a0y, a1y);
            split2(v.z, a0z, a1z); split2(v.w, a0w, a1w);
            __half2 p0a = __halves2half2(a0x, a0y), p0b = __halves2half2(a0z, a0w);
            __half2 p1a = __halves2half2(a1x, a1y), p1b = __halves2half2(a1z, a1w);
            uint2 u0, u1;
            u0.x = *(uint32_t*)&p0a; u0.y = *(uint32_t*)&p0b;
            u1.x = *(uint32_t*)&p1a; u1.y = *(uint32_t*)&p1b;
            *(uint2*)(dst + xr * ROWB + xh * 32 + q * 8)        = u0;
            *(uint2*)(dst + (64 + xr) * ROWB + xh * 32 + q * 8) = u1;
        }
    };
    auto ldg_x = [&](float4* xv, int kblk) {
#pragma unroll
        for (int i = 0; i < 4; ++i)
            xv[i] = *(const float4*)(gx + xgo + (size_t)kblk * 128 + i * 16);
    };

    // ---- preamble ----
#pragma unroll
    for (int i = 0; i < 8; ++i) cp16s(sbase + smoffB[i], gw + goffB[i]);   // B[0]
    asm volatile("cp.async.commit_group;");
    if (tid < 128) {
        ldg_x(xbuf[0], 0);
        sts_x(dsm, xbuf[0]);            // A[0] into stage 0
        ldg_x(xbuf[1], 1);              // x[1] for iter 0's STS
    }
    asm volatile("cp.async.wait_group 0;");
    __syncthreads();

    for (int kb = 0; kb < NKB; ++kb) {
        const uint32_t cur = sbase + (kb & 1) * STAGEB;
        char* nxtp = dsm + ((kb + 1) & 1) * STAGEB;
        const bool has_next = (kb + 1 < NKB);

        if (has_next) {
            const uint32_t kb1 = (uint32_t)(kb + 1);
#pragma unroll
            for (int i = 0; i < 8; ++i) cp16s(sbase + ((kb + 1) & 1) * STAGEB + smoffB[i] - 0,
                                              gw + goffB[i] + kb1 * 64);
            asm volatile("cp.async.commit_group;");
        }

        // ---- MMAs for stage kb ----
#pragma unroll
        for (int s = 0; s < 2; ++s) {
            uint32_t af[2][2][4];
#pragma unroll
            for (int p = 0; p < 2; ++p)
#pragma unroll
                for (int mf = 0; mf < 2; ++mf) {
                    uint32_t addr = cur
                                  + (p * 64 + warp_m * 32 + mf * 16 + a_row) * ROWB
                                  + (s * 16 + a_col) * 2;
                    ldsm4(af[p][mf], addr);
                }
#pragma unroll
            for (int pb = 0; pb < 2; ++pb) {
                uint32_t bf[4][4];
#pragma unroll
                for (int np = 0; np < 4; ++np) {
                    uint32_t addr = cur
                                  + (128 + pb * 256 + warp_n * 64 + np * 16 + b_row) * ROWB
                                  + (s * 16 + b_col) * 2;
                    ldsm4(bf[np], addr);
                }
                const int na = 2 - pb;
#pragma unroll
                for (int pa = 0; pa < 2; ++pa) {
                    if (pa >= na) break;
#pragma unroll
                    for (int mf = 0; mf < 2; ++mf)
#pragma unroll
                        for (int nf = 0; nf < 8; ++nf)
                            mma16816(acc[mf][nf], af[pa][mf], &bf[nf >> 1][(nf & 1) * 2]);
                }
            }
        }

        // ---- off critical path: stage kb+1's A planes + x prefetch ----
        if (tid < 128) {
            if (has_next) sts_x(nxtp, xbuf[(kb + 1) & 1]);
            if (kb + 2 < NKB) ldg_x(xbuf[kb & 1], kb + 2);
        }
        if (has_next) asm volatile("cp.async.wait_group 0;");
        __syncthreads();
    }

    // ---- epilogue: accs -> smem logits ----
#pragma unroll
    for (int mf = 0; mf < 2; ++mf)
#pragma unroll
        for (int nf = 0; nf < 8; ++nf) {
            const int row = warp_m * 32 + mf * 16 + (lane >> 2);
            const int col = warp_n * 64 + nf * 8 + (lane & 3) * 2;
            *(float2*)&slog[(size_t)row * SLSTR + col] =
                make_float2(acc[mf][nf][0], acc[mf][nf][1]);
            *(float2*)&slog[(size_t)(row + 8) * SLSTR + col] =
                make_float2(acc[mf][nf][2], acc[mf][nf][3]);
        }
    __syncthreads();

    // ---- routing: 2 groups of 128 threads, 32 tokens each ----
    const int g   = tid >> 7;
    const int e   = tid & 127;
    const int gw2 = (tid >> 5) & 3;
    const int gl  = tid & 31;

    __shared__ float s4m1[2][4], s4m2[2][4], s4s1[2][4], s4s2[2][4];
    __shared__ float sbg[2][NEXP];
    __shared__ float bvhlg[2][NEXP];
    __shared__ float candpg[2][NCAND];
    __shared__ float candflg[2][NCAND];
    __shared__ int   candeg[2][NCAND];
    __shared__ float candlg[2][NCAND];
    __shared__ float toppg[2][TOPK];
    __shared__ int   topeg[2][TOPK];

    for (int it = 0; it < 32; ++it) {
        const int t  = g * 32 + it;
        const int tg = m0 + t;
        float fl = slog[(size_t)t * SLSTR + e];
        float bl = slog[(size_t)t * SLSTR + 128 + e];

        float wm1 = warpMax(fl);
        float wm2 = warpMax(bl);
        if (gl == 0) { s4m1[g][gw2] = wm1; s4m2[g][gw2] = wm2; }
        GBAR(g);
        float m1 = fmaxf(fmaxf(s4m1[g][0], s4m1[g][1]), fmaxf(s4m1[g][2], s4m1[g][3]));
        float m2 = fmaxf(fmaxf(s4m2[g][0], s4m2[g][1]), fmaxf(s4m2[g][2], s4m2[g][3]));
        float p = exp_precise(fl - m1);
        float q = exp_precise(bl - m2);
        float ws1 = warpSum(p);
        float ws2 = warpSum(q);
        if (gl == 0) { s4s1[g][gw2] = ws1; s4s2[g][gw2] = ws2; }
        GBAR(g);
        float s1 = s4s1[g][0] + s4s1[g][1] + s4s1[g][2] + s4s1[g][3];
        float s2 = s4s2[g][0] + s4s2[g][1] + s4s2[g][2] + s4s2[g][3];
        float prob  = __fdiv_rn(p, s1);
        out[(size_t)tg * NEXP + e] = prob;
        float bprob = __fdiv_rn(q, s2);
        sbg[g][e] = bprob;
        GBAR(g);

        int r = 0;
#pragma unroll 8
        for (int j = 0; j < NEXP; ++j) {
            float v = sbg[g][j];
            r += (v > bprob) || (v == bprob && j < e);
        }
        bvhlg[g][r] = bl;
        if (r < NCAND) { candeg[g][r] = e; candpg[g][r] = prob; candflg[g][r] = fl; }
        GBAR(g);

        if (e < NCAND) {
            float cp = candpg[g][e];
            int r2 = 0;
#pragma unroll
            for (int j = 0; j < NCAND; ++j) {
                float v = candpg[g][j];
                r2 += (v > cp) || (v == cp && j < e);
            }
            candlg[g][r2] = candflg[g][e];
            if (r2 < TOPK) { topeg[g][r2] = candeg[g][e]; toppg[g][r2] = cp; }
        }
        GBAR(g);

        if (e == 0) {
            float s = 0.f;
#pragma unroll
            for (int k = 0; k < TOPK; ++k) s += toppg[g][k];
            float* ov = out + (size_t)TOKENS * NEXP + (size_t)tg * TOPK;
            float* oi = out + (size_t)TOKENS * NEXP + (size_t)TOKENS * TOPK + (size_t)tg * TOPK;
#pragma unroll
            for (int k = 0; k < TOPK; ++k) {
                ov[k] = __fdiv_rn(toppg[g][k], s);
                oi[k] = (float)topeg[g][k];
            }
            bool flag = (bvhlg[g][NCAND - 1] - bvhlg[g][NCAND] < TAU_L) ||
                        (candlg[g][TOPK - 1] - candlg[g][TOPK] < TAU_L);
#pragma unroll
            for (int k = 0; k < TOPK - 1; ++k)
                flag |= (candlg[g][k] - candlg[g][k + 1] < TAU_L);
            if (flag) {
                int pos = atomicAdd(&g_nflag, 1);
                g_flags[pos] = tg;
            }
        }
        GBAR(g);
    }
}

// ---------------------------------------------------------------------------
// Certified recompute + re-route, 4 tokens per block (verbatim round-11).
// ---------------------------------------------------------------------------
#define RC_XS   0
#define RC_WS   32768
#define RC_SL   (32768 + 49152)
#define RC_SMEM (RC_SL + 4096)

__global__ __launch_bounds__(256, 2) void recroute_kernel(const float* __restrict__ x,
                                                          float* __restrict__ out) {
    extern __shared__ char rsm[];
    float* xs = (float*)(rsm + RC_XS);          // [4][2048]
    float* wsm = (float*)(rsm + RC_WS);         // [3][16*256]
    float* sl = (float*)(rsm + RC_SL);          // [4][256]
    const uint32_t xsb = smem_u32(xs);
    const uint32_t wsb = smem_u32(wsm);

    __shared__ float s4[4];
    __shared__ float sb[NEXP];
    __shared__ float cand_p[NCAND];
    __shared__ int   cand_e[NCAND];
    __shared__ float top_p[TOPK];
    __shared__ int   top_e[TOPK];

    const int tid  = threadIdx.x;
    const int lane = tid & 31;
    const int wrp  = tid >> 5;
    const int cnt  = g_nflag;
    const int ngroups = (cnt + 3) >> 2;
    const int j   = tid >> 6;          // token slot 0..3
    const int n4  = (tid & 63) * 4;    // 4 consecutive experts

    for (int gi = blockIdx.x; gi < ngroups; gi += gridDim.x) {
        int tlist[4];
#pragma unroll
        for (int j2 = 0; j2 < 4; ++j2) {
            int idx = gi * 4 + j2;
            tlist[j2] = g_flags[idx < cnt ? idx : cnt - 1];
        }

        asm volatile("cp.async.wait_group 0;");
        __syncthreads();

#pragma unroll
        for (int i = 0; i < 8; ++i) {
            int cid = tid + i * 256;
            int j2 = cid >> 9, c = cid & 511;
            cp16s(xsb + j2 * 8192 + c * 16,
                  (const char*)(x + (size_t)tlist[j2] * HIDDEN) + c * 16);
        }
#pragma unroll
        for (int i = 0; i < 4; ++i) {
            int cid = tid + i * 256;
            cp16s(wsb + cid * 16, (const char*)g_wT + cid * 16);
        }
        asm volatile("cp.async.commit_group;");
#pragma unroll
        for (int i = 0; i < 4; ++i) {
            int cid = tid + i * 256;
            cp16s(wsb + 16384 + cid * 16, (const char*)g_wT + 16384 + cid * 16);
        }
        asm volatile("cp.async.commit_group;");

        float acc[4] = {0.f, 0.f, 0.f, 0.f};
        float cmp[4] = {0.f, 0.f, 0.f, 0.f};

        for (int kb = 0; kb < 128; ++kb) {
            asm volatile("cp.async.wait_group 1;");
            __syncthreads();
            if (kb + 2 < 128) {
                uint32_t buf = (uint32_t)((kb + 2) % 3) * 16384;
                const char* gsrc = (const char*)g_wT + (size_t)(kb + 2) * 16384;
#pragma unroll
                for (int i = 0; i < 4; ++i) {
                    int cid = tid + i * 256;
                    cp16s(wsb + buf + cid * 16, gsrc + cid * 16);
                }
                asm volatile("cp.async.commit_group;");
            }
            const float* wcur = wsm + (kb % 3) * 4096;
            const float* xrow = xs + j * 2048 + kb * 16;
            float bp[4] = {0.f, 0.f, 0.f, 0.f};
#pragma unroll
            for (int k = 0; k < 16; ++k) {
                float xv = xrow[k];
                float4 w4 = *(const float4*)&wcur[k * NOUT + n4];
                bp[0] = fmaf(xv, w4.x, bp[0]);
                bp[1] = fmaf(xv, w4.y, bp[1]);
                bp[2] = fmaf(xv, w4.z, bp[2]);
                bp[3] = fmaf(xv, w4.w, bp[3]);
            }
#pragma unroll
            for (int c = 0; c < 4; ++c) {
                float y = bp[c] - cmp[c];
                float s = acc[c] + y;
                cmp[c] = (s - acc[c]) - y;
                acc[c] = s;
            }
        }
#pragma unroll
        for (int c = 0; c < 4; ++c) sl[j * 256 + n4 + c] = acc[c];
        __syncthreads();

        for (int j2 = 0; j2 < 4; ++j2) {
            if (gi * 4 + j2 >= cnt) break;
            const int t = tlist[j2];
            const float* slj = sl + j2 * 256;
            const int e = tid & 127;
            const bool active = tid < 128;
            float fl = slj[e];
            float bl = slj[128 + e];

            float wm = active ? warpMax(fl) : 0.f;
            if (active && lane == 0) s4[wrp] = wm;
            __syncthreads();
            float m1 = fmaxf(fmaxf(s4[0], s4[1]), fmaxf(s4[2], s4[3]));
            __syncthreads();
            float p = exp_precise(fl - m1);
            float wsum = active ? warpSum(p) : 0.f;
            if (active && lane == 0) s4[wrp] = wsum;
            __syncthreads();
            float s1 = s4[0] + s4[1] + s4[2] + s4[3];
            __syncthreads();
            float prob = __fdiv_rn(p, s1);
            if (active) out[(size_t)t * NEXP + e] = prob;

            wm = active ? warpMax(bl) : 0.f;
            if (active && lane == 0) s4[wrp] = wm;
            __syncthreads();
            float m2 = fmaxf(fmaxf(s4[0], s4[1]), fmaxf(s4[2], s4[3]));
            __syncthreads();
            float q = exp_precise(bl - m2);
            wsum = active ? warpSum(q) : 0.f;
            if (active && lane == 0) s4[wrp] = wsum;
            __syncthreads();
            float s2 = s4[0] + s4[1] + s4[2] + s4[3];
            float bprob = __fdiv_rn(q, s2);
            if (active) sb[e] = bprob;
            __syncthreads();

            if (active) {
                int r = 0;
#pragma unroll 8
                for (int jj = 0; jj < NEXP; ++jj) {
                    float v = sb[jj];
                    r += (v > bprob) || (v == bprob && jj < e);
                }
                if (r < NCAND) { cand_e[r] = e; cand_p[r] = prob; }
            }
            __syncthreads();

            if (tid < NCAND) {
                float cp = cand_p[tid];
                int r2 = 0;
#pragma unroll
                for (int jj = 0; jj < NCAND; ++jj) {
                    float v = cand_p[jj];
                    r2 += (v > cp) || (v == cp && jj < tid);
                }
                if (r2 < TOPK) { top_e[r2] = cand_e[tid]; top_p[r2] = cp; }
            }
            __syncthreads();

            if (tid == 0) {
                float s = 0.f;
#pragma unroll
                for (int k = 0; k < TOPK; ++k) s += top_p[k];
                float* ov = out + (size_t)TOKENS * NEXP + (size_t)t * TOPK;
                float* oi = out + (size_t)TOKENS * NEXP + (size_t)TOKENS * TOPK + (size_t)t * TOPK;
#pragma unroll
                for (int k = 0; k < TOPK; ++k) {
                    ov[k] = __fdiv_rn(top_p[k], s);
                    oi[k] = (float)top_e[k];
                }
            }
            __syncthreads();
        }
    }
}

// ---------------------------------------------------------------------------
extern "C" void kernel_launch(void* const* d_in, const int* in_sizes, int n_in,
                              void* d_out, int out_size) {
    const float* x  = (const float*)d_in[0];
    const float* wo = (const float*)d_in[1];
    const float* wb = (const float*)d_in[2];
    float* out = (float*)d_out;

    cudaFuncSetAttribute(fused_kernel, cudaFuncAttributeMaxDynamicSharedMemorySize, DSMEM);
    cudaFuncSetAttribute(recroute_kernel, cudaFuncAttributeMaxDynamicSharedMemorySize, RC_SMEM);

    wprep_kernel<<<(NOUT * HIDDEN / 4 + 255) / 256, 256>>>(wo, wb);
    fused_kernel<<<TOKENS / 64, 256, DSMEM>>>(x, out);
    recroute_kernel<<<512, 256, RC_SMEM>>>(x, out);
}

// round 14
// speedup vs baseline: 3.7988x; 1.0672x over previous
#include <cuda_runtime.h>
#include <cuda_fp16.h>
#include <cstdint>

#define TOKENS 16384
#define HIDDEN 2048
#define NEXP   128
#define NOUT   256
#define TOPK   8
#define NCAND  32
#define TAU_L  6e-5f

typedef unsigned long long u64;

// ---------------- scratch (no allocs allowed) ----------------
__device__ float g_wT[HIDDEN * NOUT];        // [h][n] fp32 (certified recompute)
#define WP0_OFF 0
#define WP1_OFF ((size_t)NOUT * HIDDEN)
__device__ __half g_planes[2 * (size_t)NOUT * HIDDEN];
__device__ int g_nflag;
__device__ int g_flags[TOKENS];

// ---------------- PTX helpers (baseline ISA only) ----------------
__device__ __forceinline__ uint32_t smem_u32(const void* p) {
    uint32_t a;
    asm("{ .reg .u64 t; cvta.to.shared.u64 t, %1; cvt.u32.u64 %0, t; }" : "=r"(a) : "l"(p));
    return a;
}
__device__ __forceinline__ void cp16s(uint32_t saddr, const void* g) {
    asm volatile("cp.async.cg.shared.global [%0], [%1], 16;" :: "r"(saddr), "l"(g));
}
__device__ __forceinline__ void ldsm4(uint32_t* r, uint32_t a) {
    asm volatile("ldmatrix.sync.aligned.m8n8.x4.shared.b16 {%0,%1,%2,%3}, [%4];"
                 : "=r"(r[0]), "=r"(r[1]), "=r"(r[2]), "=r"(r[3]) : "r"(a));
}
__device__ __forceinline__ void mma16816(float* d, const uint32_t* a, const uint32_t* b) {
    asm volatile(
        "mma.sync.aligned.m16n8k16.row.col.f32.f16.f16.f32 "
        "{%0,%1,%2,%3}, {%4,%5,%6,%7}, {%8,%9}, {%0,%1,%2,%3};"
        : "+f"(d[0]), "+f"(d[1]), "+f"(d[2]), "+f"(d[3])
        : "r"(a[0]), "r"(a[1]), "r"(a[2]), "r"(a[3]), "r"(b[0]), "r"(b[1]));
}
#define GBAR(g) asm volatile("bar.sync %0, %1;" :: "r"((g) + 1), "r"(128) : "memory")

// fp16 2-plane split: v = p0 + p1 + O(2^-22 v)
__device__ __forceinline__ void split2(float v, __half& a0, __half& a1) {
    a0 = __float2half_rn(v);
    a1 = __float2half_rn(v - __half2float(a0));
}

// ---------------------------------------------------------------------------
// Weight prep: fp16 planes + fp32 transpose + flag reset
// ---------------------------------------------------------------------------
__global__ void wprep_kernel(const float* __restrict__ wo,
                             const float* __restrict__ wb) {
    if (blockIdx.x == 0 && threadIdx.x == 0) g_nflag = 0;
    size_t i4 = (size_t)blockIdx.x * 256 + threadIdx.x;
    if (i4 >= (size_t)NOUT * HIDDEN / 4) return;
    int n  = (int)(i4 / (HIDDEN / 4));
    int c4 = (int)(i4 % (HIDDEN / 4)) * 4;
    const float* src = (n < NEXP) ? &wo[(size_t)n * HIDDEN + c4]
                                  : &wb[(size_t)(n - NEXP) * HIDDEN + c4];
    float4 v = *(const float4*)src;
    __half a0[4], a1[4];
    split2(v.x, a0[0], a1[0]);
    split2(v.y, a0[1], a1[1]);
    split2(v.z, a0[2], a1[2]);
    split2(v.w, a0[3], a1[3]);
    size_t e = (size_t)n * HIDDEN + c4;
    *(uint2*)&g_planes[WP0_OFF + e] = *(uint2*)a0;
    *(uint2*)&g_planes[WP1_OFF + e] = *(uint2*)a1;
    g_wT[(size_t)(c4 + 0) * NOUT + n] = v.x;
    g_wT[(size_t)(c4 + 1) * NOUT + n] = v.y;
    g_wT[(size_t)(c4 + 2) * NOUT + n] = v.z;
    g_wT[(size_t)(c4 + 3) * NOUT + n] = v.w;
}

// ---------------------------------------------------------------------------
// Precise exp + warp reductions
// ---------------------------------------------------------------------------
__device__ __forceinline__ float exp_precise(float xx) {
    float kf = rintf(xx * 1.4426950408889634f);
    float r  = fmaf(kf, -0.693145751953125f, xx);
    r = fmaf(kf, -1.42860676533018704e-06f, r);
    float p = 1.98412698412698413e-04f;
    p = fmaf(p, r, 1.38888888888888889e-03f);
    p = fmaf(p, r, 8.33333333333333333e-03f);
    p = fmaf(p, r, 4.16666666666666667e-02f);
    p = fmaf(p, r, 1.66666666666666667e-01f);
    p = fmaf(p, r, 0.5f);
    p = fmaf(p, r, 1.0f);
    p = fmaf(p, r, 1.0f);
    int ki = (int)kf;
    return p * __int_as_float((ki + 127) << 23);
}
__device__ __forceinline__ float warpMax(float v) {
#pragma unroll
    for (int o = 16; o; o >>= 1) v = fmaxf(v, __shfl_xor_sync(0xffffffffu, v, o));
    return v;
}
__device__ __forceinline__ float warpSum(float v) {
#pragma unroll
    for (int o = 16; o; o >>= 1) v += __shfl_xor_sync(0xffffffffu, v, o);
    return v;
}

// ---------------------------------------------------------------------------
// Fused GEMM + routing — VERBATIM the round-11 (363.7us certified) kernel.
// CTA = 64 tokens x 256 experts, 256 threads (2x4 warps). 1 sync/stage;
// x cp.async'd raw and converted to fp16 planes off the tensor critical path.
// ---------------------------------------------------------------------------
#define ROWB    80
#define STAGEB  (640 * ROWB)          // 51200 B
#define X32OFF  (2 * STAGEB)          // 102400
#define NKB     (HIDDEN / 32)         // 64 stages
#define SLSTR   258
#define DSMEM   (X32OFF + 64 * 128)   // 110592 B

__global__ __launch_bounds__(256, 2) void fused_kernel(const float* __restrict__ x,
                                                       float* __restrict__ out) {
    extern __shared__ char dsm[];
    const uint32_t sbase = smem_u32(dsm);
    const uint32_t x32b  = sbase + X32OFF;
    float* slog = (float*)dsm;

    const int tid    = threadIdx.x;
    const int lane   = tid & 31;
    const int wid    = tid >> 5;
    const int warp_m = wid & 1;
    const int warp_n = wid >> 1;
    const int m0     = blockIdx.x * 64;

    uint32_t smoffB[8], goffB[8];
#pragma unroll
    for (int i = 0; i < 8; ++i) {
        int cid = tid + i * 256;
        int row = cid >> 2, seg = cid & 3;
        smoffB[i] = (uint32_t)((128 + row) * ROWB + seg * 16);
        int q = row >> 8, r = row & 255;
        goffB[i] = (uint32_t)(((q ? WP1_OFF : WP0_OFF) + (size_t)r * HIDDEN) * 2 + seg * 16);
    }
    const char* gw = (const char*)g_planes;
    const char* gx = (const char*)x;

    const int xr = tid >> 1;
    const int xh = tid & 1;
    const uint32_t xsm = x32b + xr * 128 + xh * 64;
    const size_t   xgo = ((size_t)(m0 + xr) * HIDDEN) * 4 + xh * 64;

    float acc[2][8][4];
#pragma unroll
    for (int mf = 0; mf < 2; ++mf)
#pragma unroll
        for (int nf = 0; nf < 8; ++nf)
#pragma unroll
            for (int c = 0; c < 4; ++c) acc[mf][nf][c] = 0.f;

    const int a_row = lane & 15;
    const int a_col = (lane >> 4) << 3;
    const int b_row = ((lane >> 4) & 1) * 8 + (lane & 7);
    const int b_col = ((lane >> 3) & 1) * 8;

    auto convert_x = [&](char* dst) {
        if (tid < 128) {
            const float4* src = (const float4*)(dsm + X32OFF + xr * 128 + xh * 64);
#pragma unroll
            for (int q = 0; q < 4; ++q) {
                float4 v = src[q];
                __half a0x, a1x, a0y, a1y, a0z, a1z, a0w, a1w;
                split2(v.x, a0x, a1x); split2(v.y, a0y, a1y);
                split2(v.z, a0z, a1z); split2(v.w, a0w, a1w);
                __half2 p0a = __halves2half2(a0x, a0y), p0b = __halves2half2(a0z, a0w);
                __half2 p1a = __halves2half2(a1x, a1y), p1b = __halves2half2(a1z, a1w);
                uint2 u0, u1;
                u0.x = *(uint32_t*)&p0a; u0.y = *(uint32_t*)&p0b;
                u1.x = *(uint32_t*)&p1a; u1.y = *(uint32_t*)&p1b;
                *(uint2*)(dst + xr * ROWB + xh * 32 + q * 8)        = u0;
                *(uint2*)(dst + (64 + xr) * ROWB + xh * 32 + q * 8) = u1;
            }
        }
    };
    auto issue_x = [&](int kblk) {
        if (tid < 128) {
#pragma unroll
            for (int i = 0; i < 4; ++i)
                cp16s(xsm + i * 16, gx + xgo + (size_t)kblk * 128 + i * 16);
        }
    };

    // ---- preamble: stage 0 ----
#pragma unroll
    for (int i = 0; i < 8; ++i) cp16s(sbase + smoffB[i], gw + goffB[i]);
    issue_x(0);
    asm volatile("cp.async.commit_group;");
    asm volatile("cp.async.wait_group 0;");
    __syncthreads();
    convert_x(dsm);
    issue_x(1);
    asm volatile("cp.async.commit_group;");

    for (int kb = 0; kb < NKB; ++kb) {
        const uint32_t cur = sbase + (kb & 1) * STAGEB;
        __syncthreads();
        if (kb + 1 < NKB) {
            const uint32_t nxt = sbase + ((kb + 1) & 1) * STAGEB;
            const uint32_t kb1 = (uint32_t)(kb + 1);
#pragma unroll
            for (int i = 0; i < 8; ++i) cp16s(nxt + smoffB[i], gw + goffB[i] + kb1 * 64);
            asm volatile("cp.async.commit_group;");
        }

#pragma unroll
        for (int s = 0; s < 2; ++s) {
            uint32_t af[2][2][4];
#pragma unroll
            for (int p = 0; p < 2; ++p)
#pragma unroll
                for (int mf = 0; mf < 2; ++mf) {
                    uint32_t addr = cur
                                  + (p * 64 + warp_m * 32 + mf * 16 + a_row) * ROWB
                                  + (s * 16 + a_col) * 2;
                    ldsm4(af[p][mf], addr);
                }
#pragma unroll
            for (int pb = 0; pb < 2; ++pb) {
                uint32_t bf[4][4];
#pragma unroll
                for (int np = 0; np < 4; ++np) {
                    uint32_t addr = cur
                                  + (128 + pb * 256 + warp_n * 64 + np * 16 + b_row) * ROWB
                                  + (s * 16 + b_col) * 2;
                    ldsm4(bf[np], addr);
                }
                const int na = 2 - pb;
#pragma unroll
                for (int pa = 0; pa < 2; ++pa) {
                    if (pa >= na) break;
#pragma unroll
                    for (int mf = 0; mf < 2; ++mf)
#pragma unroll
                        for (int nf = 0; nf < 8; ++nf)
                            mma16816(acc[mf][nf], af[pa][mf], &bf[nf >> 1][(nf & 1) * 2]);
                }
            }
        }

        asm volatile("cp.async.wait_group 0;");
        if (kb + 1 < NKB) convert_x(dsm + ((kb + 1) & 1) * STAGEB);
        if (kb + 2 < NKB) {
            issue_x(kb + 2);
            asm volatile("cp.async.commit_group;");
        }
    }

    // ---- epilogue: accs -> smem logits ----
    __syncthreads();
#pragma unroll
    for (int mf = 0; mf < 2; ++mf)
#pragma unroll
        for (int nf = 0; nf < 8; ++nf) {
            const int row = warp_m * 32 + mf * 16 + (lane >> 2);
            const int col = warp_n * 64 + nf * 8 + (lane & 3) * 2;
            *(float2*)&slog[(size_t)row * SLSTR + col] =
                make_float2(acc[mf][nf][0], acc[mf][nf][1]);
            *(float2*)&slog[(size_t)(row + 8) * SLSTR + col] =
                make_float2(acc[mf][nf][2], acc[mf][nf][3]);
        }
    __syncthreads();

    // ---- routing: 2 groups of 128 threads, 32 tokens each ----
    const int g   = tid >> 7;
    const int e   = tid & 127;
    const int gw2 = (tid >> 5) & 3;
    const int gl  = tid & 31;

    __shared__ float s4m1[2][4], s4m2[2][4], s4s1[2][4], s4s2[2][4];
    __shared__ float sbg[2][NEXP];
    __shared__ float bvhlg[2][NEXP];
    __shared__ float candpg[2][NCAND];
    __shared__ float candflg[2][NCAND];
    __shared__ int   candeg[2][NCAND];
    __shared__ float candlg[2][NCAND];
    __shared__ float toppg[2][TOPK];
    __shared__ int   topeg[2][TOPK];

    for (int it = 0; it < 32; ++it) {
        const int t  = g * 32 + it;
        const int tg = m0 + t;
        float fl = slog[(size_t)t * SLSTR + e];
        float bl = slog[(size_t)t * SLSTR + 128 + e];

        float wm1 = warpMax(fl);
        float wm2 = warpMax(bl);
        if (gl == 0) { s4m1[g][gw2] = wm1; s4m2[g][gw2] = wm2; }
        GBAR(g);
        float m1 = fmaxf(fmaxf(s4m1[g][0], s4m1[g][1]), fmaxf(s4m1[g][2], s4m1[g][3]));
        float m2 = fmaxf(fmaxf(s4m2[g][0], s4m2[g][1]), fmaxf(s4m2[g][2], s4m2[g][3]));
        float p = exp_precise(fl - m1);
        float q = exp_precise(bl - m2);
        float ws1 = warpSum(p);
        float ws2 = warpSum(q);
        if (gl == 0) { s4s1[g][gw2] = ws1; s4s2[g][gw2] = ws2; }
        GBAR(g);
        float s1 = s4s1[g][0] + s4s1[g][1] + s4s1[g][2] + s4s1[g][3];
        float s2 = s4s2[g][0] + s4s2[g][1] + s4s2[g][2] + s4s2[g][3];
        float prob  = __fdiv_rn(p, s1);
        out[(size_t)tg * NEXP + e] = prob;
        float bprob = __fdiv_rn(q, s2);
        sbg[g][e] = bprob;
        GBAR(g);

        int r = 0;
#pragma unroll 8
        for (int j = 0; j < NEXP; ++j) {
            float v = sbg[g][j];
            r += (v > bprob) || (v == bprob && j < e);
        }
        bvhlg[g][r] = bl;
        if (r < NCAND) { candeg[g][r] = e; candpg[g][r] = prob; candflg[g][r] = fl; }
        GBAR(g);

        if (e < NCAND) {
            float cp = candpg[g][e];
            int r2 = 0;
#pragma unroll
            for (int j = 0; j < NCAND; ++j) {
                float v = candpg[g][j];
                r2 += (v > cp) || (v == cp && j < e);
            }
            candlg[g][r2] = candflg[g][e];
            if (r2 < TOPK) { topeg[g][r2] = candeg[g][e]; toppg[g][r2] = cp; }
        }
        GBAR(g);

        if (e == 0) {
            float s = 0.f;
#pragma unroll
            for (int k = 0; k < TOPK; ++k) s += toppg[g][k];
            float* ov = out + (size_t)TOKENS * NEXP + (size_t)tg * TOPK;
            float* oi = out + (size_t)TOKENS * NEXP + (size_t)TOKENS * TOPK + (size_t)tg * TOPK;
#pragma unroll
            for (int k = 0; k < TOPK; ++k) {
                ov[k] = __fdiv_rn(toppg[g][k], s);
                oi[k] = (float)topeg[g][k];
            }
            bool flag = (bvhlg[g][NCAND - 1] - bvhlg[g][NCAND] < TAU_L) ||
                        (candlg[g][TOPK - 1] - candlg[g][TOPK] < TAU_L);
#pragma unroll
            for (int k = 0; k < TOPK - 1; ++k)
                flag |= (candlg[g][k] - candlg[g][k + 1] < TAU_L);
            if (flag) {
                int pos = atomicAdd(&g_nflag, 1);
                g_flags[pos] = tg;
            }
        }
        GBAR(g);
    }
}

// ---------------------------------------------------------------------------
// Certified recompute + re-route, 4 tokens per block.
// NEW: 32-k stages (64 stages), 4-buffer ring, depth-3 prefetch -> latency
// hidden. Each stage does TWO verbatim 16-k block-partial + Kahan merges
// (op-identical to the certified chain).
// smem: xs 32768 | ws 4x32768=131072 | sl 4096  = 167936 B
// ---------------------------------------------------------------------------
#define RC_XS   0
#define RC_WS   32768
#define RC_SL   (RC_WS + 131072)
#define RC_SMEM (RC_SL + 4096)

__global__ __launch_bounds__(256, 1) void recroute_kernel(const float* __restrict__ x,
                                                          float* __restrict__ out) {
    extern __shared__ char rsm[];
    float* xs  = (float*)(rsm + RC_XS);     // [4][2048]
    float* wsm = (float*)(rsm + RC_WS);     // [4][32*256]
    float* sl  = (float*)(rsm + RC_SL);     // [4][256]
    const uint32_t xsb = smem_u32(xs);
    const uint32_t wsb = smem_u32(wsm);

    __shared__ float s4[4];
    __shared__ float sb[NEXP];
    __shared__ float cand_p[NCAND];
    __shared__ int   cand_e[NCAND];
    __shared__ float top_p[TOPK];
    __shared__ int   top_e[TOPK];

    const int tid  = threadIdx.x;
    const int lane = tid & 31;
    const int wrp  = tid >> 5;
    const int cnt  = g_nflag;
    const int ngroups = (cnt + 3) >> 2;
    const int j   = tid >> 6;          // token slot 0..3
    const int n4  = (tid & 63) * 4;    // 4 consecutive experts

    // stage = 32 k = 32768 B of g_wT; 2048 chunks, 8 per thread
    auto issue_w = [&](int st) {
        uint32_t buf = (uint32_t)(st & 3) * 32768;
        const char* gsrc = (const char*)g_wT + (size_t)st * 32768;
#pragma unroll
        for (int i = 0; i < 8; ++i) {
            int cid = tid + i * 256;
            cp16s(wsb + buf + cid * 16, gsrc + cid * 16);
        }
        asm volatile("cp.async.commit_group;");
    };

    for (int gi = blockIdx.x; gi < ngroups; gi += gridDim.x) {
        int tlist[4];
#pragma unroll
        for (int j2 = 0; j2 < 4; ++j2) {
            int idx = gi * 4 + j2;
            tlist[j2] = g_flags[idx < cnt ? idx : cnt - 1];
        }

        asm volatile("cp.async.wait_group 0;");   // drain previous group
        __syncthreads();

        // xs: 4 rows x 8 KB = 2048 chunks (grouped with w stage 0)
#pragma unroll
        for (int i = 0; i < 8; ++i) {
            int cid = tid + i * 256;
            int j2 = cid >> 9, c = cid & 511;
            cp16s(xsb + j2 * 8192 + c * 16,
                  (const char*)(x + (size_t)tlist[j2] * HIDDEN) + c * 16);
        }
        issue_w(0);            // commit includes xs
        issue_w(1);
        issue_w(2);

        float acc[4] = {0.f, 0.f, 0.f, 0.f};
        float cmp[4] = {0.f, 0.f, 0.f, 0.f};

        for (int st = 0; st < 64; ++st) {          // 32-k stages
            asm volatile("cp.async.wait_group 2;");
            __syncthreads();
            if (st + 3 < 64) issue_w(st + 3);

            const float* wcur = wsm + (st & 3) * 8192;
            const float* xrow = xs + j * 2048 + st * 32;
#pragma unroll
            for (int sub = 0; sub < 2; ++sub) {
                float bp[4] = {0.f, 0.f, 0.f, 0.f};
#pragma unroll
                for (int k = 0; k < 16; ++k) {
                    float xv = xrow[sub * 16 + k];
                    float4 w4 = *(const float4*)&wcur[(sub * 16 + k) * NOUT + n4];
                    bp[0] = fmaf(xv, w4.x, bp[0]);
                    bp[1] = fmaf(xv, w4.y, bp[1]);
                    bp[2] = fmaf(xv, w4.z, bp[2]);
                    bp[3] = fmaf(xv, w4.w, bp[3]);
                }
#pragma unroll
                for (int c = 0; c < 4; ++c) {
                    float y = bp[c] - cmp[c];
                    float s = acc[c] + y;
                    cmp[c] = (s - acc[c]) - y;
                    acc[c] = s;
                }
            }
        }
#pragma unroll
        for (int c = 0; c < 4; ++c) sl[j * 256 + n4 + c] = acc[c];
        __syncthreads();

        for (int j2 = 0; j2 < 4; ++j2) {
            if (gi * 4 + j2 >= cnt) break;
            const int t = tlist[j2];
            const float* slj = sl + j2 * 256;
            const int e = tid & 127;
            const bool active = tid < 128;
            float fl = slj[e];
            float bl = slj[128 + e];

            float wm = active ? warpMax(fl) : 0.f;
            if (active && lane == 0) s4[wrp] = wm;
            __syncthreads();
            float m1 = fmaxf(fmaxf(s4[0], s4[1]), fmaxf(s4[2], s4[3]));
            __syncthreads();
            float p = exp_precise(fl - m1);
            float wsum = active ? warpSum(p) : 0.f;
            if (active && lane == 0) s4[wrp] = wsum;
            __syncthreads();
            float s1 = s4[0] + s4[1] + s4[2] + s4[3];
            __syncthreads();
            float prob = __fdiv_rn(p, s1);
            if (active) out[(size_t)t * NEXP + e] = prob;

            wm = active ? warpMax(bl) : 0.f;
            if (active && lane == 0) s4[wrp] = wm;
            __syncthreads();
            float m2 = fmaxf(fmaxf(s4[0], s4[1]), fmaxf(s4[2], s4[3]));
            __syncthreads();
            float q = exp_precise(bl - m2);
            wsum = active ? warpSum(q) : 0.f;
            if (active && lane == 0) s4[wrp] = wsum;
            __syncthreads();
            float s2 = s4[0] + s4[1] + s4[2] + s4[3];
            float bprob = __fdiv_rn(q, s2);
            if (active) sb[e] = bprob;
            __syncthreads();

            if (active) {
                int r = 0;
#pragma unroll 8
                for (int jj = 0; jj < NEXP; ++jj) {
                    float v = sb[jj];
                    r += (v > bprob) || (v == bprob && jj < e);
                }
                if (r < NCAND) { cand_e[r] = e; cand_p[r] = prob; }
            }
            __syncthreads();

            if (tid < NCAND) {
                float cp = cand_p[tid];
                int r2 = 0;
#pragma unroll
                for (int jj = 0; jj < NCAND; ++jj) {
                    float v = cand_p[jj];
                    r2 += (v > cp) || (v == cp && jj < tid);
                }
                if (r2 < TOPK) { top_e[r2] = cand_e[tid]; top_p[r2] = cp; }
            }
            __syncthreads();

            if (tid == 0) {
                float s = 0.f;
#pragma unroll
                for (int k = 0; k < TOPK; ++k) s += top_p[k];
                float* ov = out + (size_t)TOKENS * NEXP + (size_t)t * TOPK;
                float* oi = out + (size_t)TOKENS * NEXP + (size_t)TOKENS * TOPK + (size_t)t * TOPK;
#pragma unroll
                for (int k = 0; k < TOPK; ++k) {
                    ov[k] = __fdiv_rn(top_p[k], s);
                    oi[k] = (float)top_e[k];
                }
            }
            __syncthreads();
        }
    }
}

// ---------------------------------------------------------------------------
extern "C" void kernel_launch(void* const* d_in, const int* in_sizes, int n_in,
                              void* d_out, int out_size) {
    const float* x  = (const float*)d_in[0];
    const float* wo = (const float*)d_in[1];
    const float* wb = (const float*)d_in[2];
    float* out = (float*)d_out;

    cudaFuncSetAttribute(fused_kernel, cudaFuncAttributeMaxDynamicSharedMemorySize, DSMEM);
    cudaFuncSetAttribute(recroute_kernel, cudaFuncAttributeMaxDynamicSharedMemorySize, RC_SMEM);

    wprep_kernel<<<(NOUT * HIDDEN / 4 + 255) / 256, 256>>>(wo, wb);
    fused_kernel<<<TOKENS / 64, 256, DSMEM>>>(x, out);
    recroute_kernel<<<512, 256, RC_SMEM>>>(x, out);
}

// round 15
// speedup vs baseline: 4.3740x; 1.1514x over previous
#include <cuda_runtime.h>
#include <cuda_fp16.h>
#include <cstdint>

#define TOKENS 16384
#define HIDDEN 2048
#define NEXP   128
#define NOUT   256
#define TOPK   8
#define NCAND  32
#define TAU_L  6e-5f

typedef unsigned long long u64;

// ---------------- scratch (no allocs allowed) ----------------
__device__ float g_wT[HIDDEN * NOUT];        // [h][n] fp32 (certified recompute)
__device__ float g_logits[TOKENS * NOUT];    // [t][n]
#define WP0_OFF 0
#define WP1_OFF ((size_t)NOUT * HIDDEN)
__device__ __half g_planes[2 * (size_t)NOUT * HIDDEN];
__device__ int g_nflag;
__device__ int g_flags[TOKENS];

// ---------------- PTX helpers (baseline ISA only) ----------------
__device__ __forceinline__ uint32_t smem_u32(const void* p) {
    uint32_t a;
    asm("{ .reg .u64 t; cvta.to.shared.u64 t, %1; cvt.u32.u64 %0, t; }" : "=r"(a) : "l"(p));
    return a;
}
__device__ __forceinline__ void cp16s(uint32_t saddr, const void* g) {
    asm volatile("cp.async.cg.shared.global [%0], [%1], 16;" :: "r"(saddr), "l"(g));
}
__device__ __forceinline__ void ldsm4(uint32_t* r, uint32_t a) {
    asm volatile("ldmatrix.sync.aligned.m8n8.x4.shared.b16 {%0,%1,%2,%3}, [%4];"
                 : "=r"(r[0]), "=r"(r[1]), "=r"(r[2]), "=r"(r[3]) : "r"(a));
}
__device__ __forceinline__ void mma16816(float* d, const uint32_t* a, const uint32_t* b) {
    asm volatile(
        "mma.sync.aligned.m16n8k16.row.col.f32.f16.f16.f32 "
        "{%0,%1,%2,%3}, {%4,%5,%6,%7}, {%8,%9}, {%0,%1,%2,%3};"
        : "+f"(d[0]), "+f"(d[1]), "+f"(d[2]), "+f"(d[3])
        : "r"(a[0]), "r"(a[1]), "r"(a[2]), "r"(a[3]), "r"(b[0]), "r"(b[1]));
}

// fp16 2-plane split: v = p0 + p1 + O(2^-22 v)
__device__ __forceinline__ void split2(float v, __half& a0, __half& a1) {
    a0 = __float2half_rn(v);
    a1 = __float2half_rn(v - __half2float(a0));
}

// ---------------------------------------------------------------------------
// Weight prep: fp16 planes + fp32 transpose + flag reset
// ---------------------------------------------------------------------------
__global__ void wprep_kernel(const float* __restrict__ wo,
                             const float* __restrict__ wb) {
    if (blockIdx.x == 0 && threadIdx.x == 0) g_nflag = 0;
    size_t i4 = (size_t)blockIdx.x * 256 + threadIdx.x;
    if (i4 >= (size_t)NOUT * HIDDEN / 4) return;
    int n  = (int)(i4 / (HIDDEN / 4));
    int c4 = (int)(i4 % (HIDDEN / 4)) * 4;
    const float* src = (n < NEXP) ? &wo[(size_t)n * HIDDEN + c4]
                                  : &wb[(size_t)(n - NEXP) * HIDDEN + c4];
    float4 v = *(const float4*)src;
    __half a0[4], a1[4];
    split2(v.x, a0[0], a1[0]);
    split2(v.y, a0[1], a1[1]);
    split2(v.z, a0[2], a1[2]);
    split2(v.w, a0[3], a1[3]);
    size_t e = (size_t)n * HIDDEN + c4;
    *(uint2*)&g_planes[WP0_OFF + e] = *(uint2*)a0;
    *(uint2*)&g_planes[WP1_OFF + e] = *(uint2*)a1;
    g_wT[(size_t)(c4 + 0) * NOUT + n] = v.x;
    g_wT[(size_t)(c4 + 1) * NOUT + n] = v.y;
    g_wT[(size_t)(c4 + 2) * NOUT + n] = v.z;
    g_wT[(size_t)(c4 + 3) * NOUT + n] = v.w;
}

// ---------------------------------------------------------------------------
// Precise exp + warp reductions
// ---------------------------------------------------------------------------
__device__ __forceinline__ float exp_precise(float xx) {
    float kf = rintf(xx * 1.4426950408889634f);
    float r  = fmaf(kf, -0.693145751953125f, xx);
    r = fmaf(kf, -1.42860676533018704e-06f, r);
    float p = 1.98412698412698413e-04f;
    p = fmaf(p, r, 1.38888888888888889e-03f);
    p = fmaf(p, r, 8.33333333333333333e-03f);
    p = fmaf(p, r, 4.16666666666666667e-02f);
    p = fmaf(p, r, 1.66666666666666667e-01f);
    p = fmaf(p, r, 0.5f);
    p = fmaf(p, r, 1.0f);
    p = fmaf(p, r, 1.0f);
    int ki = (int)kf;
    return p * __int_as_float((ki + 127) << 23);
}
__device__ __forceinline__ float warpMax(float v) {
#pragma unroll
    for (int o = 16; o; o >>= 1) v = fmaxf(v, __shfl_xor_sync(0xffffffffu, v, o));
    return v;
}
__device__ __forceinline__ float warpSum(float v) {
#pragma unroll
    for (int o = 16; o; o >>= 1) v += __shfl_xor_sync(0xffffffffu, v, o);
    return v;
}

// ---------------------------------------------------------------------------
// GEMM (R8 geometry + in-kernel x convert): grid (TOKENS/128, 2).
// CTA = 128 tokens x 128 experts, 256 threads (4x2 warps), warp tile 32x64.
// Stage rows: A planes rows 0..255 (2x128), B planes rows 256..511 (2x128).
// x staged raw fp32 (single 16 KB buffer, per-thread half-row ownership),
// converted to fp16 planes off the tensor critical path. 1 sync/stage.
// Per-output k-order identical to all certified rounds -> bitwise logits.
// ---------------------------------------------------------------------------
#define ROWB    80
#define STAGEB  (512 * ROWB)          // 40960 B
#define X32OFF  (2 * STAGEB)          // 81920
#define NKB     (HIDDEN / 32)         // 64 stages
#define DSMEM   (X32OFF + 128 * 128)  // 98304 B

__global__ __launch_bounds__(256, 2) void tc_gemm_kernel(const float* __restrict__ x) {
    extern __shared__ char dsm[];
    const uint32_t sbase = smem_u32(dsm);
    const uint32_t x32b  = sbase + X32OFF;

    const int tid    = threadIdx.x;
    const int lane   = tid & 31;
    const int wid    = tid >> 5;
    const int warp_m = wid & 3;      // 0..3 -> 32-token slab
    const int warp_n = wid >> 2;     // 0..1 -> 64-expert slab
    const int m0     = blockIdx.x * 128;
    const int n0     = blockIdx.y * 128;

    // B loader: 2 planes x 128 rows x 4 segs = 1024 chunks, 4 per thread
    uint32_t smoffB[4], goffB[4];
#pragma unroll
    for (int i = 0; i < 4; ++i) {
        int cid = tid + i * 256;
        int row = cid >> 2, seg = cid & 3;       // row 0..255
        smoffB[i] = (uint32_t)((256 + row) * ROWB + seg * 16);
        int q = row >> 7, r = row & 127;
        goffB[i] = (uint32_t)(((q ? WP1_OFF : WP0_OFF) + (size_t)(n0 + r) * HIDDEN) * 2 + seg * 16);
    }
    const char* gw = (const char*)g_planes;
    const char* gx = (const char*)x;

    // x ownership: all 256 threads; thread owns half-row (xr, xh), 64 B/stage
    const int xr = tid >> 1;         // 0..127
    const int xh = tid & 1;
    const uint32_t xsm = x32b + xr * 128 + xh * 64;
    const size_t   xgo = ((size_t)(m0 + xr) * HIDDEN) * 4 + xh * 64;

    float acc[2][8][4];
#pragma unroll
    for (int mf = 0; mf < 2; ++mf)
#pragma unroll
        for (int nf = 0; nf < 8; ++nf)
#pragma unroll
            for (int c = 0; c < 4; ++c) acc[mf][nf][c] = 0.f;

    const int a_row = lane & 15;
    const int a_col = (lane >> 4) << 3;
    const int b_row = ((lane >> 4) & 1) * 8 + (lane & 7);
    const int b_col = ((lane >> 3) & 1) * 8;

    auto convert_x = [&](char* dst) {
        const float4* src = (const float4*)(dsm + X32OFF + xr * 128 + xh * 64);
#pragma unroll
        for (int q = 0; q < 4; ++q) {
            float4 v = src[q];
            __half a0x, a1x, a0y, a1y, a0z, a1z, a0w, a1w;
            split2(v.x, a0x, a1x); split2(v.y, a0y, a1y);
            split2(v.z, a0z, a1z); split2(v.w, a0w, a1w);
            __half2 p0a = __halves2half2(a0x, a0y), p0b = __halves2half2(a0z, a0w);
            __half2 p1a = __halves2half2(a1x, a1y), p1b = __halves2half2(a1z, a1w);
            uint2 u0, u1;
            u0.x = *(uint32_t*)&p0a; u0.y = *(uint32_t*)&p0b;
            u1.x = *(uint32_t*)&p1a; u1.y = *(uint32_t*)&p1b;
            *(uint2*)(dst + xr * ROWB + xh * 32 + q * 8)         = u0;
            *(uint2*)(dst + (128 + xr) * ROWB + xh * 32 + q * 8) = u1;
        }
    };
    auto issue_x = [&](int kblk) {
#pragma unroll
        for (int i = 0; i < 4; ++i)
            cp16s(xsm + i * 16, gx + xgo + (size_t)kblk * 128 + i * 16);
    };

    // ---- preamble: stage 0 ----
#pragma unroll
    for (int i = 0; i < 4; ++i) cp16s(sbase + smoffB[i], gw + goffB[i]);
    issue_x(0);
    asm volatile("cp.async.commit_group;");
    asm volatile("cp.async.wait_group 0;");
    __syncthreads();
    convert_x(dsm);
    issue_x(1);
    asm volatile("cp.async.commit_group;");

    for (int kb = 0; kb < NKB; ++kb) {
        const uint32_t cur = sbase + (kb & 1) * STAGEB;
        __syncthreads();
        if (kb + 1 < NKB) {
            const uint32_t nxt = sbase + ((kb + 1) & 1) * STAGEB;
            const uint32_t kb1 = (uint32_t)(kb + 1);
#pragma unroll
            for (int i = 0; i < 4; ++i) cp16s(nxt + smoffB[i], gw + goffB[i] + kb1 * 64);
            asm volatile("cp.async.commit_group;");
        }

        // ---- MMAs for stage kb (certified order) ----
#pragma unroll
        for (int s = 0; s < 2; ++s) {
            uint32_t af[2][2][4];
#pragma unroll
            for (int p = 0; p < 2; ++p)
#pragma unroll
                for (int mf = 0; mf < 2; ++mf) {
                    uint32_t addr = cur
                                  + (p * 128 + warp_m * 32 + mf * 16 + a_row) * ROWB
                                  + (s * 16 + a_col) * 2;
                    ldsm4(af[p][mf], addr);
                }
#pragma unroll
            for (int pb = 0; pb < 2; ++pb) {
                uint32_t bf[4][4];
#pragma unroll
                for (int np = 0; np < 4; ++np) {
                    uint32_t addr = cur
                                  + (256 + pb * 128 + warp_n * 64 + np * 16 + b_row) * ROWB
                                  + (s * 16 + b_col) * 2;
                    ldsm4(bf[np], addr);
                }
                const int na = 2 - pb;
#pragma unroll
                for (int pa = 0; pa < 2; ++pa) {
                    if (pa >= na) break;
#pragma unroll
                    for (int mf = 0; mf < 2; ++mf)
#pragma unroll
                        for (int nf = 0; nf < 8; ++nf)
                            mma16816(acc[mf][nf], af[pa][mf], &bf[nf >> 1][(nf & 1) * 2]);
                }
            }
        }

        // ---- off critical path: wait loads, convert next A, issue next x ----
        asm volatile("cp.async.wait_group 0;");
        if (kb + 1 < NKB) convert_x(dsm + ((kb + 1) & 1) * STAGEB);
        if (kb + 2 < NKB) {
            issue_x(kb + 2);
            asm volatile("cp.async.commit_group;");
        }
    }

    // ---- epilogue: accs -> g_logits (R8 layout) ----
#pragma unroll
    for (int mf = 0; mf < 2; ++mf)
#pragma unroll
        for (int nf = 0; nf < 8; ++nf) {
            const int row = m0 + warp_m * 32 + mf * 16 + (lane >> 2);
            const int col = n0 + warp_n * 64 + nf * 8 + (lane & 3) * 2;
            *(float2*)&g_logits[(size_t)row * NOUT + col] =
                make_float2(acc[mf][nf][0], acc[mf][nf][1]);
            *(float2*)&g_logits[(size_t)(row + 8) * NOUT + col] =
                make_float2(acc[mf][nf][2], acc[mf][nf][3]);
        }
}

// ---------------------------------------------------------------------------
// route_all: 1 block (128 threads) per token, merged dual reductions + audit.
// ---------------------------------------------------------------------------
__global__ __launch_bounds__(128) void route_all_kernel(float* __restrict__ out) {
    const int t    = blockIdx.x;
    const int e    = threadIdx.x;
    const int wrp  = e >> 5;
    const int lane = e & 31;

    __shared__ float s4m1[4], s4m2[4], s4s1[4], s4s2[4];
    __shared__ float sb[NEXP];
    __shared__ float bvhl[NEXP];
    __shared__ float cand_p[NCAND];
    __shared__ float cand_fl[NCAND];
    __shared__ int   cand_e[NCAND];
    __shared__ float candl[NCAND];
    __shared__ float top_p[TOPK];
    __shared__ int   top_e[TOPK];

    float fl = g_logits[(size_t)t * NOUT + e];
    float bl = g_logits[(size_t)t * NOUT + NEXP + e];

    float wm1 = warpMax(fl);
    float wm2 = warpMax(bl);
    if (lane == 0) { s4m1[wrp] = wm1; s4m2[wrp] = wm2; }
    __syncthreads();
    float m1 = fmaxf(fmaxf(s4m1[0], s4m1[1]), fmaxf(s4m1[2], s4m1[3]));
    float m2 = fmaxf(fmaxf(s4m2[0], s4m2[1]), fmaxf(s4m2[2], s4m2[3]));
    float p = exp_precise(fl - m1);
    float q = exp_precise(bl - m2);
    float ws1 = warpSum(p);
    float ws2 = warpSum(q);
    if (lane == 0) { s4s1[wrp] = ws1; s4s2[wrp] = ws2; }
    __syncthreads();
    float s1 = s4s1[0] + s4s1[1] + s4s1[2] + s4s1[3];
    float s2 = s4s2[0] + s4s2[1] + s4s2[2] + s4s2[3];
    float prob  = __fdiv_rn(p, s1);
    out[(size_t)t * NEXP + e] = prob;
    float bprob = __fdiv_rn(q, s2);
    sb[e] = bprob;
    __syncthreads();

    int r = 0;
#pragma unroll 8
    for (int j = 0; j < NEXP; ++j) {
        float v = sb[j];
        r += (v > bprob) || (v == bprob && j < e);
    }
    bvhl[r] = bl;
    if (r < NCAND) { cand_e[r] = e; cand_p[r] = prob; cand_fl[r] = fl; }
    __syncthreads();

    if (e < NCAND) {
        float cp = cand_p[e];
        int r2 = 0;
#pragma unroll
        for (int j = 0; j < NCAND; ++j) {
            float v = cand_p[j];
            r2 += (v > cp) || (v == cp && j < e);
        }
        candl[r2] = cand_fl[e];
        if (r2 < TOPK) { top_e[r2] = cand_e[e]; top_p[r2] = cp; }
    }
    __syncthreads();

    if (e == 0) {
        float s = 0.f;
#pragma unroll
        for (int k = 0; k < TOPK; ++k) s += top_p[k];
        float* ov = out + (size_t)TOKENS * NEXP + (size_t)t * TOPK;
        float* oi = out + (size_t)TOKENS * NEXP + (size_t)TOKENS * TOPK + (size_t)t * TOPK;
#pragma unroll
        for (int k = 0; k < TOPK; ++k) {
            ov[k] = __fdiv_rn(top_p[k], s);
            oi[k] = (float)top_e[k];
        }
        bool flag = (bvhl[NCAND - 1] - bvhl[NCAND] < TAU_L) ||
                    (candl[TOPK - 1] - candl[TOPK] < TAU_L);
#pragma unroll
        for (int k = 0; k < TOPK - 1; ++k)
            flag |= (candl[k] - candl[k + 1] < TAU_L);
        if (flag) {
            int pos = atomicAdd(&g_nflag, 1);
            g_flags[pos] = t;
        }
    }
}

// ---------------------------------------------------------------------------
// Certified recompute + re-route, 4 tokens per block (verbatim round-14).
// 32-k stages, 4-buffer ring, depth-3 prefetch.
// ---------------------------------------------------------------------------
#define RC_XS   0
#define RC_WS   32768
#define RC_SL   (RC_WS + 131072)
#define RC_SMEM (RC_SL + 4096)

__global__ __launch_bounds__(256, 1) void recroute_kernel(const float* __restrict__ x,
                                                          float* __restrict__ out) {
    extern __shared__ char rsm[];
    float* xs  = (float*)(rsm + RC_XS);     // [4][2048]
    float* wsm = (float*)(rsm + RC_WS);     // [4][32*256]
    float* sl  = (float*)(rsm + RC_SL);     // [4][256]
    const uint32_t xsb = smem_u32(xs);
    const uint32_t wsb = smem_u32(wsm);

    __shared__ float s4[4];
    __shared__ float sb[NEXP];
    __shared__ float cand_p[NCAND];
    __shared__ int   cand_e[NCAND];
    __shared__ float top_p[TOPK];
    __shared__ int   top_e[TOPK];

    const int tid  = threadIdx.x;
    const int lane = tid & 31;
    const int wrp  = tid >> 5;
    const int cnt  = g_nflag;
    const int ngroups = (cnt + 3) >> 2;
    const int j   = tid >> 6;
    const int n4  = (tid & 63) * 4;

    auto issue_w = [&](int st) {
        uint32_t buf = (uint32_t)(st & 3) * 32768;
        const char* gsrc = (const char*)g_wT + (size_t)st * 32768;
#pragma unroll
        for (int i = 0; i < 8; ++i) {
            int cid = tid + i * 256;
            cp16s(wsb + buf + cid * 16, gsrc + cid * 16);
        }
        asm volatile("cp.async.commit_group;");
    };

    for (int gi = blockIdx.x; gi < ngroups; gi += gridDim.x) {
        int tlist[4];
#pragma unroll
        for (int j2 = 0; j2 < 4; ++j2) {
            int idx = gi * 4 + j2;
            tlist[j2] = g_flags[idx < cnt ? idx : cnt - 1];
        }

        asm volatile("cp.async.wait_group 0;");
        __syncthreads();

#pragma unroll
        for (int i = 0; i < 8; ++i) {
            int cid = tid + i * 256;
            int j2 = cid >> 9, c = cid & 511;
            cp16s(xsb + j2 * 8192 + c * 16,
                  (const char*)(x + (size_t)tlist[j2] * HIDDEN) + c * 16);
        }
        issue_w(0);
        issue_w(1);
        issue_w(2);

        float acc[4] = {0.f, 0.f, 0.f, 0.f};
        float cmp[4] = {0.f, 0.f, 0.f, 0.f};

        for (int st = 0; st < 64; ++st) {
            asm volatile("cp.async.wait_group 2;");
            __syncthreads();
            if (st + 3 < 64) issue_w(st + 3);

            const float* wcur = wsm + (st & 3) * 8192;
            const float* xrow = xs + j * 2048 + st * 32;
#pragma unroll
            for (int sub = 0; sub < 2; ++sub) {
                float bp[4] = {0.f, 0.f, 0.f, 0.f};
#pragma unroll
                for (int k = 0; k < 16; ++k) {
                    float xv = xrow[sub * 16 + k];
                    float4 w4 = *(const float4*)&wcur[(sub * 16 + k) * NOUT + n4];
                    bp[0] = fmaf(xv, w4.x, bp[0]);
                    bp[1] = fmaf(xv, w4.y, bp[1]);
                    bp[2] = fmaf(xv, w4.z, bp[2]);
                    bp[3] = fmaf(xv, w4.w, bp[3]);
                }
#pragma unroll
                for (int c = 0; c < 4; ++c) {
                    float y = bp[c] - cmp[c];
                    float s = acc[c] + y;
                    cmp[c] = (s - acc[c]) - y;
                    acc[c] = s;
                }
            }
        }
#pragma unroll
        for (int c = 0; c < 4; ++c) sl[j * 256 + n4 + c] = acc[c];
        __syncthreads();

        for (int j2 = 0; j2 < 4; ++j2) {
            if (gi * 4 + j2 >= cnt) break;
            const int t = tlist[j2];
            const float* slj = sl + j2 * 256;
            const int e = tid & 127;
            const bool active = tid < 128;
            float fl = slj[e];
            float bl = slj[128 + e];

            float wm = active ? warpMax(fl) : 0.f;
            if (active && lane == 0) s4[wrp] = wm;
            __syncthreads();
            float m1 = fmaxf(fmaxf(s4[0], s4[1]), fmaxf(s4[2], s4[3]));
            __syncthreads();
            float p = exp_precise(fl - m1);
            float wsum = active ? warpSum(p) : 0.f;
            if (active && lane == 0) s4[wrp] = wsum;
            __syncthreads();
            float s1 = s4[0] + s4[1] + s4[2] + s4[3];
            __syncthreads();
            float prob = __fdiv_rn(p, s1);
            if (active) out[(size_t)t * NEXP + e] = prob;

            wm = active ? warpMax(bl) : 0.f;
            if (active && lane == 0) s4[wrp] = wm;
            __syncthreads();
            float m2 = fmaxf(fmaxf(s4[0], s4[1]), fmaxf(s4[2], s4[3]));
            __syncthreads();
            float q = exp_precise(bl - m2);
            wsum = active ? warpSum(q) : 0.f;
            if (active && lane == 0) s4[wrp] = wsum;
            __syncthreads();
            float s2 = s4[0] + s4[1] + s4[2] + s4[3];
            float bprob = __fdiv_rn(q, s2);
            if (active) sb[e] = bprob;
            __syncthreads();

            if (active) {
                int r = 0;
#pragma unroll 8
                for (int jj = 0; jj < NEXP; ++jj) {
                    float v = sb[jj];
                    r += (v > bprob) || (v == bprob && jj < e);
                }
                if (r < NCAND) { cand_e[r] = e; cand_p[r] = prob; }
            }
            __syncthreads();

            if (tid < NCAND) {
                float cp = cand_p[tid];
                int r2 = 0;
#pragma unroll
                for (int jj = 0; jj < NCAND; ++jj) {
                    float v = cand_p[jj];
                    r2 += (v > cp) || (v == cp && jj < tid);
                }
                if (r2 < TOPK) { top_e[r2] = cand_e[tid]; top_p[r2] = cp; }
            }
            __syncthreads();

            if (tid == 0) {
                float s = 0.f;
#pragma unroll
                for (int k = 0; k < TOPK; ++k) s += top_p[k];
                float* ov = out + (size_t)TOKENS * NEXP + (size_t)t * TOPK;
                float* oi = out + (size_t)TOKENS * NEXP + (size_t)TOKENS * TOPK + (size_t)t * TOPK;
#pragma unroll
                for (int k = 0; k < TOPK; ++k) {
                    ov[k] = __fdiv_rn(top_p[k], s);
                    oi[k] = (float)top_e[k];
                }
            }
            __syncthreads();
        }
    }
}

// ---------------------------------------------------------------------------
extern "C" void kernel_launch(void* const* d_in, const int* in_sizes, int n_in,
                              void* d_out, int out_size) {
    const float* x  = (const float*)d_in[0];
    const float* wo = (const float*)d_in[1];
    const float* wb = (const float*)d_in[2];
    float* out = (float*)d_out;

    cudaFuncSetAttribute(tc_gemm_kernel, cudaFuncAttributeMaxDynamicSharedMemorySize, DSMEM);
    cudaFuncSetAttribute(recroute_kernel, cudaFuncAttributeMaxDynamicSharedMemorySize, RC_SMEM);

    wprep_kernel<<<(NOUT * HIDDEN / 4 + 255) / 256, 256>>>(wo, wb);
    tc_gemm_kernel<<<dim3(TOKENS / 128, 2), 256, DSMEM>>>(x);
    route_all_kernel<<<TOKENS, 128>>>(out);
    recroute_kernel<<<512, 256, RC_SMEM>>>(x, out);
}

// round 16
// speedup vs baseline: 4.5268x; 1.0349x over previous
#include <cuda_runtime.h>
#include <cuda_fp16.h>
#include <cstdint>

#define TOKENS 16384
#define HIDDEN 2048
#define NEXP   128
#define NOUT   256
#define TOPK   8
#define NCAND  32
#define TAU_L  6e-5f

typedef unsigned long long u64;

// ---------------- scratch (no allocs allowed) ----------------
__device__ float g_wT[HIDDEN * NOUT];        // [h][n] fp32 (certified recompute)
__device__ float g_logits[TOKENS * NOUT];    // [t][n]
#define WP0_OFF 0
#define WP1_OFF ((size_t)NOUT * HIDDEN)
__device__ __half g_planes[2 * (size_t)NOUT * HIDDEN];
__device__ int g_nflag;
__device__ int g_flags[TOKENS];

// ---------------- PTX helpers (baseline ISA only) ----------------
__device__ __forceinline__ uint32_t smem_u32(const void* p) {
    uint32_t a;
    asm("{ .reg .u64 t; cvta.to.shared.u64 t, %1; cvt.u32.u64 %0, t; }" : "=r"(a) : "l"(p));
    return a;
}
__device__ __forceinline__ void cp16s(uint32_t saddr, const void* g) {
    asm volatile("cp.async.cg.shared.global [%0], [%1], 16;" :: "r"(saddr), "l"(g));
}
__device__ __forceinline__ void ldsm4(uint32_t* r, uint32_t a) {
    asm volatile("ldmatrix.sync.aligned.m8n8.x4.shared.b16 {%0,%1,%2,%3}, [%4];"
                 : "=r"(r[0]), "=r"(r[1]), "=r"(r[2]), "=r"(r[3]) : "r"(a));
}
__device__ __forceinline__ void mma16816(float* d, const uint32_t* a, const uint32_t* b) {
    asm volatile(
        "mma.sync.aligned.m16n8k16.row.col.f32.f16.f16.f32 "
        "{%0,%1,%2,%3}, {%4,%5,%6,%7}, {%8,%9}, {%0,%1,%2,%3};"
        : "+f"(d[0]), "+f"(d[1]), "+f"(d[2]), "+f"(d[3])
        : "r"(a[0]), "r"(a[1]), "r"(a[2]), "r"(a[3]), "r"(b[0]), "r"(b[1]));
}

// fp16 2-plane split: v = p0 + p1 + O(2^-22 v)
__device__ __forceinline__ void split2(float v, __half& a0, __half& a1) {
    a0 = __float2half_rn(v);
    a1 = __float2half_rn(v - __half2float(a0));
}

// ---------------------------------------------------------------------------
// Weight prep: fp16 planes + fp32 transpose + flag reset
// ---------------------------------------------------------------------------
__global__ void wprep_kernel(const float* __restrict__ wo,
                             const float* __restrict__ wb) {
    if (blockIdx.x == 0 && threadIdx.x == 0) g_nflag = 0;
    size_t i4 = (size_t)blockIdx.x * 256 + threadIdx.x;
    if (i4 >= (size_t)NOUT * HIDDEN / 4) return;
    int n  = (int)(i4 / (HIDDEN / 4));
    int c4 = (int)(i4 % (HIDDEN / 4)) * 4;
    const float* src = (n < NEXP) ? &wo[(size_t)n * HIDDEN + c4]
                                  : &wb[(size_t)(n - NEXP) * HIDDEN + c4];
    float4 v = *(const float4*)src;
    __half a0[4], a1[4];
    split2(v.x, a0[0], a1[0]);
    split2(v.y, a0[1], a1[1]);
    split2(v.z, a0[2], a1[2]);
    split2(v.w, a0[3], a1[3]);
    size_t e = (size_t)n * HIDDEN + c4;
    *(uint2*)&g_planes[WP0_OFF + e] = *(uint2*)a0;
    *(uint2*)&g_planes[WP1_OFF + e] = *(uint2*)a1;
    g_wT[(size_t)(c4 + 0) * NOUT + n] = v.x;
    g_wT[(size_t)(c4 + 1) * NOUT + n] = v.y;
    g_wT[(size_t)(c4 + 2) * NOUT + n] = v.z;
    g_wT[(size_t)(c4 + 3) * NOUT + n] = v.w;
}

// ---------------------------------------------------------------------------
// Precise exp + warp reductions
// ---------------------------------------------------------------------------
__device__ __forceinline__ float exp_precise(float xx) {
    float kf = rintf(xx * 1.4426950408889634f);
    float r  = fmaf(kf, -0.693145751953125f, xx);
    r = fmaf(kf, -1.42860676533018704e-06f, r);
    float p = 1.98412698412698413e-04f;
    p = fmaf(p, r, 1.38888888888888889e-03f);
    p = fmaf(p, r, 8.33333333333333333e-03f);
    p = fmaf(p, r, 4.16666666666666667e-02f);
    p = fmaf(p, r, 1.66666666666666667e-01f);
    p = fmaf(p, r, 0.5f);
    p = fmaf(p, r, 1.0f);
    p = fmaf(p, r, 1.0f);
    int ki = (int)kf;
    return p * __int_as_float((ki + 127) << 23);
}
__device__ __forceinline__ float warpMax(float v) {
#pragma unroll
    for (int o = 16; o; o >>= 1) v = fmaxf(v, __shfl_xor_sync(0xffffffffu, v, o));
    return v;
}
__device__ __forceinline__ float warpSum(float v) {
#pragma unroll
    for (int o = 16; o; o >>= 1) v += __shfl_xor_sync(0xffffffffu, v, o);
    return v;
}

// ---------------------------------------------------------------------------
// GEMM — VERBATIM round-15 (certified): grid (TOKENS/128, 2).
// CTA = 128 tokens x 128 experts, 256 threads (4x2 warps), warp tile 32x64.
// ---------------------------------------------------------------------------
#define ROWB    80
#define STAGEB  (512 * ROWB)          // 40960 B
#define X32OFF  (2 * STAGEB)          // 81920
#define NKB     (HIDDEN / 32)         // 64 stages
#define DSMEM   (X32OFF + 128 * 128)  // 98304 B

__global__ __launch_bounds__(256, 2) void tc_gemm_kernel(const float* __restrict__ x) {
    extern __shared__ char dsm[];
    const uint32_t sbase = smem_u32(dsm);
    const uint32_t x32b  = sbase + X32OFF;

    const int tid    = threadIdx.x;
    const int lane   = tid & 31;
    const int wid    = tid >> 5;
    const int warp_m = wid & 3;
    const int warp_n = wid >> 2;
    const int m0     = blockIdx.x * 128;
    const int n0     = blockIdx.y * 128;

    uint32_t smoffB[4], goffB[4];
#pragma unroll
    for (int i = 0; i < 4; ++i) {
        int cid = tid + i * 256;
        int row = cid >> 2, seg = cid & 3;
        smoffB[i] = (uint32_t)((256 + row) * ROWB + seg * 16);
        int q = row >> 7, r = row & 127;
        goffB[i] = (uint32_t)(((q ? WP1_OFF : WP0_OFF) + (size_t)(n0 + r) * HIDDEN) * 2 + seg * 16);
    }
    const char* gw = (const char*)g_planes;
    const char* gx = (const char*)x;

    const int xr = tid >> 1;
    const int xh = tid & 1;
    const uint32_t xsm = x32b + xr * 128 + xh * 64;
    const size_t   xgo = ((size_t)(m0 + xr) * HIDDEN) * 4 + xh * 64;

    float acc[2][8][4];
#pragma unroll
    for (int mf = 0; mf < 2; ++mf)
#pragma unroll
        for (int nf = 0; nf < 8; ++nf)
#pragma unroll
            for (int c = 0; c < 4; ++c) acc[mf][nf][c] = 0.f;

    const int a_row = lane & 15;
    const int a_col = (lane >> 4) << 3;
    const int b_row = ((lane >> 4) & 1) * 8 + (lane & 7);
    const int b_col = ((lane >> 3) & 1) * 8;

    auto convert_x = [&](char* dst) {
        const float4* src = (const float4*)(dsm + X32OFF + xr * 128 + xh * 64);
#pragma unroll
        for (int q = 0; q < 4; ++q) {
            float4 v = src[q];
            __half a0x, a1x, a0y, a1y, a0z, a1z, a0w, a1w;
            split2(v.x, a0x, a1x); split2(v.y, a0y, a1y);
            split2(v.z, a0z, a1z); split2(v.w, a0w, a1w);
            __half2 p0a = __halves2half2(a0x, a0y), p0b = __halves2half2(a0z, a0w);
            __half2 p1a = __halves2half2(a1x, a1y), p1b = __halves2half2(a1z, a1w);
            uint2 u0, u1;
            u0.x = *(uint32_t*)&p0a; u0.y = *(uint32_t*)&p0b;
            u1.x = *(uint32_t*)&p1a; u1.y = *(uint32_t*)&p1b;
            *(uint2*)(dst + xr * ROWB + xh * 32 + q * 8)         = u0;
            *(uint2*)(dst + (128 + xr) * ROWB + xh * 32 + q * 8) = u1;
        }
    };
    auto issue_x = [&](int kblk) {
#pragma unroll
        for (int i = 0; i < 4; ++i)
            cp16s(xsm + i * 16, gx + xgo + (size_t)kblk * 128 + i * 16);
    };

#pragma unroll
    for (int i = 0; i < 4; ++i) cp16s(sbase + smoffB[i], gw + goffB[i]);
    issue_x(0);
    asm volatile("cp.async.commit_group;");
    asm volatile("cp.async.wait_group 0;");
    __syncthreads();
    convert_x(dsm);
    issue_x(1);
    asm volatile("cp.async.commit_group;");

    for (int kb = 0; kb < NKB; ++kb) {
        const uint32_t cur = sbase + (kb & 1) * STAGEB;
        __syncthreads();
        if (kb + 1 < NKB) {
            const uint32_t nxt = sbase + ((kb + 1) & 1) * STAGEB;
            const uint32_t kb1 = (uint32_t)(kb + 1);
#pragma unroll
            for (int i = 0; i < 4; ++i) cp16s(nxt + smoffB[i], gw + goffB[i] + kb1 * 64);
            asm volatile("cp.async.commit_group;");
        }

#pragma unroll
        for (int s = 0; s < 2; ++s) {
            uint32_t af[2][2][4];
#pragma unroll
            for (int p = 0; p < 2; ++p)
#pragma unroll
                for (int mf = 0; mf < 2; ++mf) {
                    uint32_t addr = cur
                                  + (p * 128 + warp_m * 32 + mf * 16 + a_row) * ROWB
                                  + (s * 16 + a_col) * 2;
                    ldsm4(af[p][mf], addr);
                }
#pragma unroll
            for (int pb = 0; pb < 2; ++pb) {
                uint32_t bf[4][4];
#pragma unroll
                for (int np = 0; np < 4; ++np) {
                    uint32_t addr = cur
                                  + (256 + pb * 128 + warp_n * 64 + np * 16 + b_row) * ROWB
                                  + (s * 16 + b_col) * 2;
                    ldsm4(bf[np], addr);
                }
                const int na = 2 - pb;
#pragma unroll
                for (int pa = 0; pa < 2; ++pa) {
                    if (pa >= na) break;
#pragma unroll
                    for (int mf = 0; mf < 2; ++mf)
#pragma unroll
                        for (int nf = 0; nf < 8; ++nf)
                            mma16816(acc[mf][nf], af[pa][mf], &bf[nf >> 1][(nf & 1) * 2]);
                }
            }
        }

        asm volatile("cp.async.wait_group 0;");
        if (kb + 1 < NKB) convert_x(dsm + ((kb + 1) & 1) * STAGEB);
        if (kb + 2 < NKB) {
            issue_x(kb + 2);
            asm volatile("cp.async.commit_group;");
        }
    }

#pragma unroll
    for (int mf = 0; mf < 2; ++mf)
#pragma unroll
        for (int nf = 0; nf < 8; ++nf) {
            const int row = m0 + warp_m * 32 + mf * 16 + (lane >> 2);
            const int col = n0 + warp_n * 64 + nf * 8 + (lane & 3) * 2;
            *(float2*)&g_logits[(size_t)row * NOUT + col] =
                make_float2(acc[mf][nf][0], acc[mf][nf][1]);
            *(float2*)&g_logits[(size_t)(row + 8) * NOUT + col] =
                make_float2(acc[mf][nf][2], acc[mf][nf][3]);
        }
}

// ---------------------------------------------------------------------------
// route_all — VERBATIM round-15.
// ---------------------------------------------------------------------------
__global__ __launch_bounds__(128) void route_all_kernel(float* __restrict__ out) {
    const int t    = blockIdx.x;
    const int e    = threadIdx.x;
    const int wrp  = e >> 5;
    const int lane = e & 31;

    __shared__ float s4m1[4], s4m2[4], s4s1[4], s4s2[4];
    __shared__ float sb[NEXP];
    __shared__ float bvhl[NEXP];
    __shared__ float cand_p[NCAND];
    __shared__ float cand_fl[NCAND];
    __shared__ int   cand_e[NCAND];
    __shared__ float candl[NCAND];
    __shared__ float top_p[TOPK];
    __shared__ int   top_e[TOPK];

    float fl = g_logits[(size_t)t * NOUT + e];
    float bl = g_logits[(size_t)t * NOUT + NEXP + e];

    float wm1 = warpMax(fl);
    float wm2 = warpMax(bl);
    if (lane == 0) { s4m1[wrp] = wm1; s4m2[wrp] = wm2; }
    __syncthreads();
    float m1 = fmaxf(fmaxf(s4m1[0], s4m1[1]), fmaxf(s4m1[2], s4m1[3]));
    float m2 = fmaxf(fmaxf(s4m2[0], s4m2[1]), fmaxf(s4m2[2], s4m2[3]));
    float p = exp_precise(fl - m1);
    float q = exp_precise(bl - m2);
    float ws1 = warpSum(p);
    float ws2 = warpSum(q);
    if (lane == 0) { s4s1[wrp] = ws1; s4s2[wrp] = ws2; }
    __syncthreads();
    float s1 = s4s1[0] + s4s1[1] + s4s1[2] + s4s1[3];
    float s2 = s4s2[0] + s4s2[1] + s4s2[2] + s4s2[3];
    float prob  = __fdiv_rn(p, s1);
    out[(size_t)t * NEXP + e] = prob;
    float bprob = __fdiv_rn(q, s2);
    sb[e] = bprob;
    __syncthreads();

    int r = 0;
#pragma unroll 8
    for (int j = 0; j < NEXP; ++j) {
        float v = sb[j];
        r += (v > bprob) || (v == bprob && j < e);
    }
    bvhl[r] = bl;
    if (r < NCAND) { cand_e[r] = e; cand_p[r] = prob; cand_fl[r] = fl; }
    __syncthreads();

    if (e < NCAND) {
        float cp = cand_p[e];
        int r2 = 0;
#pragma unroll
        for (int j = 0; j < NCAND; ++j) {
            float v = cand_p[j];
            r2 += (v > cp) || (v == cp && j < e);
        }
        candl[r2] = cand_fl[e];
        if (r2 < TOPK) { top_e[r2] = cand_e[e]; top_p[r2] = cp; }
    }
    __syncthreads();

    if (e == 0) {
        float s = 0.f;
#pragma unroll
        for (int k = 0; k < TOPK; ++k) s += top_p[k];
        float* ov = out + (size_t)TOKENS * NEXP + (size_t)t * TOPK;
        float* oi = out + (size_t)TOKENS * NEXP + (size_t)TOKENS * TOPK + (size_t)t * TOPK;
#pragma unroll
        for (int k = 0; k < TOPK; ++k) {
            ov[k] = __fdiv_rn(top_p[k], s);
            oi[k] = (float)top_e[k];
        }
        bool flag = (bvhl[NCAND - 1] - bvhl[NCAND] < TAU_L) ||
                    (candl[TOPK - 1] - candl[TOPK] < TAU_L);
#pragma unroll
        for (int k = 0; k < TOPK - 1; ++k)
            flag |= (candl[k] - candl[k + 1] < TAU_L);
        if (flag) {
            int pos = atomicAdd(&g_nflag, 1);
            g_flags[pos] = t;
        }
    }
}

// ---------------------------------------------------------------------------
// Certified recompute + re-route, 4 tokens per block.
// NEW mapping: thread = ONE expert (n = tid), carries all 4 tokens' chains.
// w read once per (k, n) -> 4x less smem w-traffic than (token, 4-expert) map.
// Per-(t,n) op sequence (16-k ascending fmaf + Kahan merge) unchanged.
// 32-k stages, 4-buffer ring, depth-3 prefetch (loader verbatim R15).
// ---------------------------------------------------------------------------
#define RC_XS   0
#define RC_WS   32768
#define RC_SL   (RC_WS + 131072)
#define RC_SMEM (RC_SL + 4096)

__global__ __launch_bounds__(256, 1) void recroute_kernel(const float* __restrict__ x,
                                                          float* __restrict__ out) {
    extern __shared__ char rsm[];
    float* xs  = (float*)(rsm + RC_XS);     // [4][2048]
    float* wsm = (float*)(rsm + RC_WS);     // [4][32*256]
    float* sl  = (float*)(rsm + RC_SL);     // [4][256]
    const uint32_t xsb = smem_u32(xs);
    const uint32_t wsb = smem_u32(wsm);

    __shared__ float s4[4];
    __shared__ float sb[NEXP];
    __shared__ float cand_p[NCAND];
    __shared__ int   cand_e[NCAND];
    __shared__ float top_p[TOPK];
    __shared__ int   top_e[TOPK];

    const int tid  = threadIdx.x;          // = expert index n
    const int lane = tid & 31;
    const int wrp  = tid >> 5;
    const int cnt  = g_nflag;
    const int ngroups = (cnt + 3) >> 2;

    auto issue_w = [&](int st) {
        uint32_t buf = (uint32_t)(st & 3) * 32768;
        const char* gsrc = (const char*)g_wT + (size_t)st * 32768;
#pragma unroll
        for (int i = 0; i < 8; ++i) {
            int cid = tid + i * 256;
            cp16s(wsb + buf + cid * 16, gsrc + cid * 16);
        }
        asm volatile("cp.async.commit_group;");
    };

    for (int gi = blockIdx.x; gi < ngroups; gi += gridDim.x) {
        int tlist[4];
#pragma unroll
        for (int j2 = 0; j2 < 4; ++j2) {
            int idx = gi * 4 + j2;
            tlist[j2] = g_flags[idx < cnt ? idx : cnt - 1];
        }

        asm volatile("cp.async.wait_group 0;");
        __syncthreads();

#pragma unroll
        for (int i = 0; i < 8; ++i) {
            int cid = tid + i * 256;
            int j2 = cid >> 9, c = cid & 511;
            cp16s(xsb + j2 * 8192 + c * 16,
                  (const char*)(x + (size_t)tlist[j2] * HIDDEN) + c * 16);
        }
        issue_w(0);
        issue_w(1);
        issue_w(2);

        float acc[4] = {0.f, 0.f, 0.f, 0.f};
        float cmp[4] = {0.f, 0.f, 0.f, 0.f};

        for (int st = 0; st < 64; ++st) {
            asm volatile("cp.async.wait_group 2;");
            __syncthreads();
            if (st + 3 < 64) issue_w(st + 3);

            const float* wcur = wsm + (st & 3) * 8192;
#pragma unroll
            for (int sub = 0; sub < 2; ++sub) {
                float bp[4] = {0.f, 0.f, 0.f, 0.f};
#pragma unroll
                for (int k4 = 0; k4 < 4; ++k4) {
                    const int kk0 = st * 32 + sub * 16 + k4 * 4;
                    float4 xv0 = *(const float4*)&xs[0 * 2048 + kk0];
                    float4 xv1 = *(const float4*)&xs[1 * 2048 + kk0];
                    float4 xv2 = *(const float4*)&xs[2 * 2048 + kk0];
                    float4 xv3 = *(const float4*)&xs[3 * 2048 + kk0];
                    const float* x0 = (const float*)&xv0;
                    const float* x1 = (const float*)&xv1;
                    const float* x2 = (const float*)&xv2;
                    const float* x3 = (const float*)&xv3;
#pragma unroll
                    for (int kk = 0; kk < 4; ++kk) {
                        float w = wcur[(sub * 16 + k4 * 4 + kk) * NOUT + tid];
                        bp[0] = fmaf(x0[kk], w, bp[0]);
                        bp[1] = fmaf(x1[kk], w, bp[1]);
                        bp[2] = fmaf(x2[kk], w, bp[2]);
                        bp[3] = fmaf(x3[kk], w, bp[3]);
                    }
                }
#pragma unroll
                for (int j2 = 0; j2 < 4; ++j2) {
                    float y = bp[j2] - cmp[j2];
                    float s = acc[j2] + y;
                    cmp[j2] = (s - acc[j2]) - y;
                    acc[j2] = s;
                }
            }
        }
#pragma unroll
        for (int j2 = 0; j2 < 4; ++j2) sl[j2 * 256 + tid] = acc[j2];
        __syncthreads();

        for (int j2 = 0; j2 < 4; ++j2) {
            if (gi * 4 + j2 >= cnt) break;
            const int t = tlist[j2];
            const float* slj = sl + j2 * 256;
            const int e = tid & 127;
            const bool active = tid < 128;
            float fl = slj[e];
            float bl = slj[128 + e];

            float wm = active ? warpMax(fl) : 0.f;
            if (active && lane == 0) s4[wrp] = wm;
            __syncthreads();
            float m1 = fmaxf(fmaxf(s4[0], s4[1]), fmaxf(s4[2], s4[3]));
            __syncthreads();
            float p = exp_precise(fl - m1);
            float wsum = active ? warpSum(p) : 0.f;
            if (active && lane == 0) s4[wrp] = wsum;
            __syncthreads();
            float s1 = s4[0] + s4[1] + s4[2] + s4[3];
            __syncthreads();
            float prob = __fdiv_rn(p, s1);
            if (active) out[(size_t)t * NEXP + e] = prob;

            wm = active ? warpMax(bl) : 0.f;
            if (active && lane == 0) s4[wrp] = wm;
            __syncthreads();
            float m2 = fmaxf(fmaxf(s4[0], s4[1]), fmaxf(s4[2], s4[3]));
            __syncthreads();
            float q = exp_precise(bl - m2);
            wsum = active ? warpSum(q) : 0.f;
            if (active && lane == 0) s4[wrp] = wsum;
            __syncthreads();
            float s2 = s4[0] + s4[1] + s4[2] + s4[3];
            float bprob = __fdiv_rn(q, s2);
            if (active) sb[e] = bprob;
            __syncthreads();

            if (active) {
                int r = 0;
#pragma unroll 8
                for (int jj = 0; jj < NEXP; ++jj) {
                    float v = sb[jj];
                    r += (v > bprob) || (v == bprob && jj < e);
                }
                if (r < NCAND) { cand_e[r] = e; cand_p[r] = prob; }
            }
            __syncthreads();

            if (tid < NCAND) {
                float cp = cand_p[tid];
                int r2 = 0;
#pragma unroll
                for (int jj = 0; jj < NCAND; ++jj) {
                    float v = cand_p[jj];
                    r2 += (v > cp) || (v == cp && jj < tid);
                }
                if (r2 < TOPK) { top_e[r2] = cand_e[tid]; top_p[r2] = cp; }
            }
            __syncthreads();

            if (tid == 0) {
                float s = 0.f;
#pragma unroll
                for (int k = 0; k < TOPK; ++k) s += top_p[k];
                float* ov = out + (size_t)TOKENS * NEXP + (size_t)t * TOPK;
                float* oi = out + (size_t)TOKENS * NEXP + (size_t)TOKENS * TOPK + (size_t)t * TOPK;
#pragma unroll
                for (int k = 0; k < TOPK; ++k) {
                    ov[k] = __fdiv_rn(top_p[k], s);
                    oi[k] = (float)top_e[k];
                }
            }
            __syncthreads();
        }
    }
}

// ---------------------------------------------------------------------------
extern "C" void kernel_launch(void* const* d_in, const int* in_sizes, int n_in,
                              void* d_out, int out_size) {
    const float* x  = (const float*)d_in[0];
    const float* wo = (const float*)d_in[1];
    const float* wb = (const float*)d_in[2];
    float* out = (float*)d_out;

    cudaFuncSetAttribute(tc_gemm_kernel, cudaFuncAttributeMaxDynamicSharedMemorySize, DSMEM);
    cudaFuncSetAttribute(recroute_kernel, cudaFuncAttributeMaxDynamicSharedMemorySize, RC_SMEM);

    wprep_kernel<<<(NOUT * HIDDEN / 4 + 255) / 256, 256>>>(wo, wb);
    tc_gemm_kernel<<<dim3(TOKENS / 128, 2), 256, DSMEM>>>(x);
    route_all_kernel<<<TOKENS, 128>>>(out);
    recroute_kernel<<<512, 256, RC_SMEM>>>(x, out);
}

// round 17
// speedup vs baseline: 4.5282x; 1.0003x over previous
#include <cuda_runtime.h>
#include <cuda_fp16.h>
#include <cstdint>

#define TOKENS 16384
#define HIDDEN 2048
#define NEXP   128
#define NOUT   256
#define TOPK   8
#define NCAND  32
#define TAU_L  2.5e-5f   // was 6e-5; >=1.9x margin over estimated max tensor error

typedef unsigned long long u64;

// ---------------- scratch (no allocs allowed) ----------------
__device__ float g_wT[HIDDEN * NOUT];        // [h][n] fp32 (certified recompute)
__device__ float g_logits[TOKENS * NOUT];    // [t][n]
#define WP0_OFF 0
#define WP1_OFF ((size_t)NOUT * HIDDEN)
__device__ __half g_planes[2 * (size_t)NOUT * HIDDEN];
__device__ int g_nflag;
__device__ int g_flags[TOKENS];

// ---------------- PTX helpers (baseline ISA only) ----------------
__device__ __forceinline__ uint32_t smem_u32(const void* p) {
    uint32_t a;
    asm("{ .reg .u64 t; cvta.to.shared.u64 t, %1; cvt.u32.u64 %0, t; }" : "=r"(a) : "l"(p));
    return a;
}
__device__ __forceinline__ void cp16s(uint32_t saddr, const void* g) {
    asm volatile("cp.async.cg.shared.global [%0], [%1], 16;" :: "r"(saddr), "l"(g));
}
__device__ __forceinline__ void ldsm4(uint32_t* r, uint32_t a) {
    asm volatile("ldmatrix.sync.aligned.m8n8.x4.shared.b16 {%0,%1,%2,%3}, [%4];"
                 : "=r"(r[0]), "=r"(r[1]), "=r"(r[2]), "=r"(r[3]) : "r"(a));
}
__device__ __forceinline__ void mma16816(float* d, const uint32_t* a, const uint32_t* b) {
    asm volatile(
        "mma.sync.aligned.m16n8k16.row.col.f32.f16.f16.f32 "
        "{%0,%1,%2,%3}, {%4,%5,%6,%7}, {%8,%9}, {%0,%1,%2,%3};"
        : "+f"(d[0]), "+f"(d[1]), "+f"(d[2]), "+f"(d[3])
        : "r"(a[0]), "r"(a[1]), "r"(a[2]), "r"(a[3]), "r"(b[0]), "r"(b[1]));
}

// fp16 2-plane split: v = p0 + p1 + O(2^-22 v)
__device__ __forceinline__ void split2(float v, __half& a0, __half& a1) {
    a0 = __float2half_rn(v);
    a1 = __float2half_rn(v - __half2float(a0));
}

// ---------------------------------------------------------------------------
// Weight prep: fp16 planes + fp32 transpose + flag reset
// ---------------------------------------------------------------------------
__global__ void wprep_kernel(const float* __restrict__ wo,
                             const float* __restrict__ wb) {
    if (blockIdx.x == 0 && threadIdx.x == 0) g_nflag = 0;
    size_t i4 = (size_t)blockIdx.x * 256 + threadIdx.x;
    if (i4 >= (size_t)NOUT * HIDDEN / 4) return;
    int n  = (int)(i4 / (HIDDEN / 4));
    int c4 = (int)(i4 % (HIDDEN / 4)) * 4;
    const float* src = (n < NEXP) ? &wo[(size_t)n * HIDDEN + c4]
                                  : &wb[(size_t)(n - NEXP) * HIDDEN + c4];
    float4 v = *(const float4*)src;
    __half a0[4], a1[4];
    split2(v.x, a0[0], a1[0]);
    split2(v.y, a0[1], a1[1]);
    split2(v.z, a0[2], a1[2]);
    split2(v.w, a0[3], a1[3]);
    size_t e = (size_t)n * HIDDEN + c4;
    *(uint2*)&g_planes[WP0_OFF + e] = *(uint2*)a0;
    *(uint2*)&g_planes[WP1_OFF + e] = *(uint2*)a1;
    g_wT[(size_t)(c4 + 0) * NOUT + n] = v.x;
    g_wT[(size_t)(c4 + 1) * NOUT + n] = v.y;
    g_wT[(size_t)(c4 + 2) * NOUT + n] = v.z;
    g_wT[(size_t)(c4 + 3) * NOUT + n] = v.w;
}

// ---------------------------------------------------------------------------
// Precise exp + warp reductions
// ---------------------------------------------------------------------------
__device__ __forceinline__ float exp_precise(float xx) {
    float kf = rintf(xx * 1.4426950408889634f);
    float r  = fmaf(kf, -0.693145751953125f, xx);
    r = fmaf(kf, -1.42860676533018704e-06f, r);
    float p = 1.98412698412698413e-04f;
    p = fmaf(p, r, 1.38888888888888889e-03f);
    p = fmaf(p, r, 8.33333333333333333e-03f);
    p = fmaf(p, r, 4.16666666666666667e-02f);
    p = fmaf(p, r, 1.66666666666666667e-01f);
    p = fmaf(p, r, 0.5f);
    p = fmaf(p, r, 1.0f);
    p = fmaf(p, r, 1.0f);
    int ki = (int)kf;
    return p * __int_as_float((ki + 127) << 23);
}
__device__ __forceinline__ float warpMax(float v) {
#pragma unroll
    for (int o = 16; o; o >>= 1) v = fmaxf(v, __shfl_xor_sync(0xffffffffu, v, o));
    return v;
}
__device__ __forceinline__ float warpSum(float v) {
#pragma unroll
    for (int o = 16; o; o >>= 1) v += __shfl_xor_sync(0xffffffffu, v, o);
    return v;
}

// ---------------------------------------------------------------------------
// GEMM — VERBATIM round-15/16 (certified): grid (TOKENS/128, 2).
// ---------------------------------------------------------------------------
#define ROWB    80
#define STAGEB  (512 * ROWB)          // 40960 B
#define X32OFF  (2 * STAGEB)          // 81920
#define NKB     (HIDDEN / 32)         // 64 stages
#define DSMEM   (X32OFF + 128 * 128)  // 98304 B

__global__ __launch_bounds__(256, 2) void tc_gemm_kernel(const float* __restrict__ x) {
    extern __shared__ char dsm[];
    const uint32_t sbase = smem_u32(dsm);
    const uint32_t x32b  = sbase + X32OFF;

    const int tid    = threadIdx.x;
    const int lane   = tid & 31;
    const int wid    = tid >> 5;
    const int warp_m = wid & 3;
    const int warp_n = wid >> 2;
    const int m0     = blockIdx.x * 128;
    const int n0     = blockIdx.y * 128;

    uint32_t smoffB[4], goffB[4];
#pragma unroll
    for (int i = 0; i < 4; ++i) {
        int cid = tid + i * 256;
        int row = cid >> 2, seg = cid & 3;
        smoffB[i] = (uint32_t)((256 + row) * ROWB + seg * 16);
        int q = row >> 7, r = row & 127;
        goffB[i] = (uint32_t)(((q ? WP1_OFF : WP0_OFF) + (size_t)(n0 + r) * HIDDEN) * 2 + seg * 16);
    }
    const char* gw = (const char*)g_planes;
    const char* gx = (const char*)x;

    const int xr = tid >> 1;
    const int xh = tid & 1;
    const uint32_t xsm = x32b + xr * 128 + xh * 64;
    const size_t   xgo = ((size_t)(m0 + xr) * HIDDEN) * 4 + xh * 64;

    float acc[2][8][4];
#pragma unroll
    for (int mf = 0; mf < 2; ++mf)
#pragma unroll
        for (int nf = 0; nf < 8; ++nf)
#pragma unroll
            for (int c = 0; c < 4; ++c) acc[mf][nf][c] = 0.f;

    const int a_row = lane & 15;
    const int a_col = (lane >> 4) << 3;
    const int b_row = ((lane >> 4) & 1) * 8 + (lane & 7);
    const int b_col = ((lane >> 3) & 1) * 8;

    auto convert_x = [&](char* dst) {
        const float4* src = (const float4*)(dsm + X32OFF + xr * 128 + xh * 64);
#pragma unroll
        for (int q = 0; q < 4; ++q) {
            float4 v = src[q];
            __half a0x, a1x, a0y, a1y, a0z, a1z, a0w, a1w;
            split2(v.x, a0x, a1x); split2(v.y, a0y, a1y);
            split2(v.z, a0z, a1z); split2(v.w, a0w, a1w);
            __half2 p0a = __halves2half2(a0x, a0y), p0b = __halves2half2(a0z, a0w);
            __half2 p1a = __halves2half2(a1x, a1y), p1b = __halves2half2(a1z, a1w);
            uint2 u0, u1;
            u0.x = *(uint32_t*)&p0a; u0.y = *(uint32_t*)&p0b;
            u1.x = *(uint32_t*)&p1a; u1.y = *(uint32_t*)&p1b;
            *(uint2*)(dst + xr * ROWB + xh * 32 + q * 8)         = u0;
            *(uint2*)(dst + (128 + xr) * ROWB + xh * 32 + q * 8) = u1;
        }
    };
    auto issue_x = [&](int kblk) {
#pragma unroll
        for (int i = 0; i < 4; ++i)
            cp16s(xsm + i * 16, gx + xgo + (size_t)kblk * 128 + i * 16);
    };

#pragma unroll
    for (int i = 0; i < 4; ++i) cp16s(sbase + smoffB[i], gw + goffB[i]);
    issue_x(0);
    asm volatile("cp.async.commit_group;");
    asm volatile("cp.async.wait_group 0;");
    __syncthreads();
    convert_x(dsm);
    issue_x(1);
    asm volatile("cp.async.commit_group;");

    for (int kb = 0; kb < NKB; ++kb) {
        const uint32_t cur = sbase + (kb & 1) * STAGEB;
        __syncthreads();
        if (kb + 1 < NKB) {
            const uint32_t nxt = sbase + ((kb + 1) & 1) * STAGEB;
            const uint32_t kb1 = (uint32_t)(kb + 1);
#pragma unroll
            for (int i = 0; i < 4; ++i) cp16s(nxt + smoffB[i], gw + goffB[i] + kb1 * 64);
            asm volatile("cp.async.commit_group;");
        }

#pragma unroll
        for (int s = 0; s < 2; ++s) {
            uint32_t af[2][2][4];
#pragma unroll
            for (int p = 0; p < 2; ++p)
#pragma unroll
                for (int mf = 0; mf < 2; ++mf) {
                    uint32_t addr = cur
                                  + (p * 128 + warp_m * 32 + mf * 16 + a_row) * ROWB
                                  + (s * 16 + a_col) * 2;
                    ldsm4(af[p][mf], addr);
                }
#pragma unroll
            for (int pb = 0; pb < 2; ++pb) {
                uint32_t bf[4][4];
#pragma unroll
                for (int np = 0; np < 4; ++np) {
                    uint32_t addr = cur
                                  + (256 + pb * 128 + warp_n * 64 + np * 16 + b_row) * ROWB
                                  + (s * 16 + b_col) * 2;
                    ldsm4(bf[np], addr);
                }
                const int na = 2 - pb;
#pragma unroll
                for (int pa = 0; pa < 2; ++pa) {
                    if (pa >= na) break;
#pragma unroll
                    for (int mf = 0; mf < 2; ++mf)
#pragma unroll
                        for (int nf = 0; nf < 8; ++nf)
                            mma16816(acc[mf][nf], af[pa][mf], &bf[nf >> 1][(nf & 1) * 2]);
                }
            }
        }

        asm volatile("cp.async.wait_group 0;");
        if (kb + 1 < NKB) convert_x(dsm + ((kb + 1) & 1) * STAGEB);
        if (kb + 2 < NKB) {
            issue_x(kb + 2);
            asm volatile("cp.async.commit_group;");
        }
    }

#pragma unroll
    for (int mf = 0; mf < 2; ++mf)
#pragma unroll
        for (int nf = 0; nf < 8; ++nf) {
            const int row = m0 + warp_m * 32 + mf * 16 + (lane >> 2);
            const int col = n0 + warp_n * 64 + nf * 8 + (lane & 3) * 2;
            *(float2*)&g_logits[(size_t)row * NOUT + col] =
                make_float2(acc[mf][nf][0], acc[mf][nf][1]);
            *(float2*)&g_logits[(size_t)(row + 8) * NOUT + col] =
                make_float2(acc[mf][nf][2], acc[mf][nf][3]);
        }
}

// ---------------------------------------------------------------------------
// route_all — VERBATIM round-16 (only TAU_L macro changed).
// ---------------------------------------------------------------------------
__global__ __launch_bounds__(128) void route_all_kernel(float* __restrict__ out) {
    const int t    = blockIdx.x;
    const int e    = threadIdx.x;
    const int wrp  = e >> 5;
    const int lane = e & 31;

    __shared__ float s4m1[4], s4m2[4], s4s1[4], s4s2[4];
    __shared__ float sb[NEXP];
    __shared__ float bvhl[NEXP];
    __shared__ float cand_p[NCAND];
    __shared__ float cand_fl[NCAND];
    __shared__ int   cand_e[NCAND];
    __shared__ float candl[NCAND];
    __shared__ float top_p[TOPK];
    __shared__ int   top_e[TOPK];

    float fl = g_logits[(size_t)t * NOUT + e];
    float bl = g_logits[(size_t)t * NOUT + NEXP + e];

    float wm1 = warpMax(fl);
    float wm2 = warpMax(bl);
    if (lane == 0) { s4m1[wrp] = wm1; s4m2[wrp] = wm2; }
    __syncthreads();
    float m1 = fmaxf(fmaxf(s4m1[0], s4m1[1]), fmaxf(s4m1[2], s4m1[3]));
    float m2 = fmaxf(fmaxf(s4m2[0], s4m2[1]), fmaxf(s4m2[2], s4m2[3]));
    float p = exp_precise(fl - m1);
    float q = exp_precise(bl - m2);
    float ws1 = warpSum(p);
    float ws2 = warpSum(q);
    if (lane == 0) { s4s1[wrp] = ws1; s4s2[wrp] = ws2; }
    __syncthreads();
    float s1 = s4s1[0] + s4s1[1] + s4s1[2] + s4s1[3];
    float s2 = s4s2[0] + s4s2[1] + s4s2[2] + s4s2[3];
    float prob  = __fdiv_rn(p, s1);
    out[(size_t)t * NEXP + e] = prob;
    float bprob = __fdiv_rn(q, s2);
    sb[e] = bprob;
    __syncthreads();

    int r = 0;
#pragma unroll 8
    for (int j = 0; j < NEXP; ++j) {
        float v = sb[j];
        r += (v > bprob) || (v == bprob && j < e);
    }
    bvhl[r] = bl;
    if (r < NCAND) { cand_e[r] = e; cand_p[r] = prob; cand_fl[r] = fl; }
    __syncthreads();

    if (e < NCAND) {
        float cp = cand_p[e];
        int r2 = 0;
#pragma unroll
        for (int j = 0; j < NCAND; ++j) {
            float v = cand_p[j];
            r2 += (v > cp) || (v == cp && j < e);
        }
        candl[r2] = cand_fl[e];
        if (r2 < TOPK) { top_e[r2] = cand_e[e]; top_p[r2] = cp; }
    }
    __syncthreads();

    if (e == 0) {
        float s = 0.f;
#pragma unroll
        for (int k = 0; k < TOPK; ++k) s += top_p[k];
        float* ov = out + (size_t)TOKENS * NEXP + (size_t)t * TOPK;
        float* oi = out + (size_t)TOKENS * NEXP + (size_t)TOKENS * TOPK + (size_t)t * TOPK;
#pragma unroll
        for (int k = 0; k < TOPK; ++k) {
            ov[k] = __fdiv_rn(top_p[k], s);
            oi[k] = (float)top_e[k];
        }
        bool flag = (bvhl[NCAND - 1] - bvhl[NCAND] < TAU_L) ||
                    (candl[TOPK - 1] - candl[TOPK] < TAU_L);
#pragma unroll
        for (int k = 0; k < TOPK - 1; ++k)
            flag |= (candl[k] - candl[k + 1] < TAU_L);
        if (flag) {
            int pos = atomicAdd(&g_nflag, 1);
            g_flags[pos] = t;
        }
    }
}

// ---------------------------------------------------------------------------
// Certified recompute + re-route — VERBATIM round-16.
// ---------------------------------------------------------------------------
#define RC_XS   0
#define RC_WS   32768
#define RC_SL   (RC_WS + 131072)
#define RC_SMEM (RC_SL + 4096)

__global__ __launch_bounds__(256, 1) void recroute_kernel(const float* __restrict__ x,
                                                          float* __restrict__ out) {
    extern __shared__ char rsm[];
    float* xs  = (float*)(rsm + RC_XS);
    float* wsm = (float*)(rsm + RC_WS);
    float* sl  = (float*)(rsm + RC_SL);
    const uint32_t xsb = smem_u32(xs);
    const uint32_t wsb = smem_u32(wsm);

    __shared__ float s4[4];
    __shared__ float sb[NEXP];
    __shared__ float cand_p[NCAND];
    __shared__ int   cand_e[NCAND];
    __shared__ float top_p[TOPK];
    __shared__ int   top_e[TOPK];

    const int tid  = threadIdx.x;
    const int lane = tid & 31;
    const int wrp  = tid >> 5;
    const int cnt  = g_nflag;
    const int ngroups = (cnt + 3) >> 2;

    auto issue_w = [&](int st) {
        uint32_t buf = (uint32_t)(st & 3) * 32768;
        const char* gsrc = (const char*)g_wT + (size_t)st * 32768;
#pragma unroll
        for (int i = 0; i < 8; ++i) {
            int cid = tid + i * 256;
            cp16s(wsb + buf + cid * 16, gsrc + cid * 16);
        }
        asm volatile("cp.async.commit_group;");
    };

    for (int gi = blockIdx.x; gi < ngroups; gi += gridDim.x) {
        int tlist[4];
#pragma unroll
        for (int j2 = 0; j2 < 4; ++j2) {
            int idx = gi * 4 + j2;
            tlist[j2] = g_flags[idx < cnt ? idx : cnt - 1];
        }

        asm volatile("cp.async.wait_group 0;");
        __syncthreads();

#pragma unroll
        for (int i = 0; i < 8; ++i) {
            int cid = tid + i * 256;
            int j2 = cid >> 9, c = cid & 511;
            cp16s(xsb + j2 * 8192 + c * 16,
                  (const char*)(x + (size_t)tlist[j2] * HIDDEN) + c * 16);
        }
        issue_w(0);
        issue_w(1);
        issue_w(2);

        float acc[4] = {0.f, 0.f, 0.f, 0.f};
        float cmp[4] = {0.f, 0.f, 0.f, 0.f};

        for (int st = 0; st < 64; ++st) {
            asm volatile("cp.async.wait_group 2;");
            __syncthreads();
            if (st + 3 < 64) issue_w(st + 3);

            const float* wcur = wsm + (st & 3) * 8192;
#pragma unroll
            for (int sub = 0; sub < 2; ++sub) {
                float bp[4] = {0.f, 0.f, 0.f, 0.f};
#pragma unroll
                for (int k4 = 0; k4 < 4; ++k4) {
                    const int kk0 = st * 32 + sub * 16 + k4 * 4;
                    float4 xv0 = *(const float4*)&xs[0 * 2048 + kk0];
                    float4 xv1 = *(const float4*)&xs[1 * 2048 + kk0];
                    float4 xv2 = *(const float4*)&xs[2 * 2048 + kk0];
                    float4 xv3 = *(const float4*)&xs[3 * 2048 + kk0];
                    const float* x0 = (const float*)&xv0;
                    const float* x1 = (const float*)&xv1;
                    const float* x2 = (const float*)&xv2;
                    const float* x3 = (const float*)&xv3;
#pragma unroll
                    for (int kk = 0; kk < 4; ++kk) {
                        float w = wcur[(sub * 16 + k4 * 4 + kk) * NOUT + tid];
                        bp[0] = fmaf(x0[kk], w, bp[0]);
                        bp[1] = fmaf(x1[kk], w, bp[1]);
                        bp[2] = fmaf(x2[kk], w, bp[2]);
                        bp[3] = fmaf(x3[kk], w, bp[3]);
                    }
                }
#pragma unroll
                for (int j2 = 0; j2 < 4; ++j2) {
                    float y = bp[j2] - cmp[j2];
                    float s = acc[j2] + y;
                    cmp[j2] = (s - acc[j2]) - y;
                    acc[j2] = s;
                }
            }
        }
#pragma unroll
        for (int j2 = 0; j2 < 4; ++j2) sl[j2 * 256 + tid] = acc[j2];
        __syncthreads();

        for (int j2 = 0; j2 < 4; ++j2) {
            if (gi * 4 + j2 >= cnt) break;
            const int t = tlist[j2];
            const float* slj = sl + j2 * 256;
            const int e = tid & 127;
            const bool active = tid < 128;
            float fl = slj[e];
            float bl = slj[128 + e];

            float wm = active ? warpMax(fl) : 0.f;
            if (active && lane == 0) s4[wrp] = wm;
            __syncthreads();
            float m1 = fmaxf(fmaxf(s4[0], s4[1]), fmaxf(s4[2], s4[3]));
            __syncthreads();
            float p = exp_precise(fl - m1);
            float wsum = active ? warpSum(p) : 0.f;
            if (active && lane == 0) s4[wrp] = wsum;
            __syncthreads();
            float s1 = s4[0] + s4[1] + s4[2] + s4[3];
            __syncthreads();
            float prob = __fdiv_rn(p, s1);
            if (active) out[(size_t)t * NEXP + e] = prob;

            wm = active ? warpMax(bl) : 0.f;
            if (active && lane == 0) s4[wrp] = wm;
            __syncthreads();
            float m2 = fmaxf(fmaxf(s4[0], s4[1]), fmaxf(s4[2], s4[3]));
            __syncthreads();
            float q = exp_precise(bl - m2);
            wsum = active ? warpSum(q) : 0.f;
            if (active && lane == 0) s4[wrp] = wsum;
            __syncthreads();
            float s2 = s4[0] + s4[1] + s4[2] + s4[3];
            float bprob = __fdiv_rn(q, s2);
            if (active) sb[e] = bprob;
            __syncthreads();

            if (active) {
                int r = 0;
#pragma unroll 8
                for (int jj = 0; jj < NEXP; ++jj) {
                    float v = sb[jj];
                    r += (v > bprob) || (v == bprob && jj < e);
                }
                if (r < NCAND) { cand_e[r] = e; cand_p[r] = prob; }
            }
            __syncthreads();

            if (tid < NCAND) {
                float cp = cand_p[tid];
                int r2 = 0;
#pragma unroll
                for (int jj = 0; jj < NCAND; ++jj) {
                    float v = cand_p[jj];
                    r2 += (v > cp) || (v == cp && jj < tid);
                }
                if (r2 < TOPK) { top_e[r2] = cand_e[tid]; top_p[r2] = cp; }
            }
            __syncthreads();

            if (tid == 0) {
                float s = 0.f;
#pragma unroll
                for (int k = 0; k < TOPK; ++k) s += top_p[k];
                float* ov = out + (size_t)TOKENS * NEXP + (size_t)t * TOPK;
                float* oi = out + (size_t)TOKENS * NEXP + (size_t)TOKENS * TOPK + (size_t)t * TOPK;
#pragma unroll
                for (int k = 0; k < TOPK; ++k) {
                    ov[k] = __fdiv_rn(top_p[k], s);
                    oi[k] = (float)top_e[k];
                }
            }
            __syncthreads();
        }
    }
}

// ---------------------------------------------------------------------------
extern "C" void kernel_launch(void* const* d_in, const int* in_sizes, int n_in,
                              void* d_out, int out_size) {
    const float* x  = (const float*)d_in[0];
    const float* wo = (const float*)d_in[1];
    const float* wb = (const float*)d_in[2];
    float* out = (float*)d_out;

    cudaFuncSetAttribute(tc_gemm_kernel, cudaFuncAttributeMaxDynamicSharedMemorySize, DSMEM);
    cudaFuncSetAttribute(recroute_kernel, cudaFuncAttributeMaxDynamicSharedMemorySize, RC_SMEM);

    wprep_kernel<<<(NOUT * HIDDEN / 4 + 255) / 256, 256>>>(wo, wb);
    tc_gemm_kernel<<<dim3(TOKENS / 128, 2), 256, DSMEM>>>(x);
    route_all_kernel<<<TOKENS, 128>>>(out);
    recroute_kernel<<<512, 256, RC_SMEM>>>(x, out);
}